// round 10
// baseline (speedup 1.0000x reference)
#include <cuda_runtime.h>
#include <math.h>
#include <stdint.h>

// Problem dims (LinearAttnBlock: B=8, C=256, H=W=64)
#define BATCH 8
#define CDIM  256
#define NDIM  4096
#define GRP   32
#define KVSPLIT 8

// ---------------- scratch (__device__ globals; no allocation allowed) ------
__device__ float  g_qkv[(size_t)BATCH * 2 * CDIM * NDIM];        // [b][q/k][c][n]
__device__ float  g_Sp [(size_t)KVSPLIT * BATCH * CDIM * CDIM];  // S split partials
__device__ float  g_S  [BATCH * CDIM * CDIM];                    // [b][c][e] = K.h^T
__device__ float  g_M  [BATCH * CDIM * CDIM];                    // [b][o][c]
__device__ float  g_U  [CDIM * CDIM];                            // wo @ Wv
__device__ float  g_wt [CDIM];                                   // wo @ bv
__device__ float  g_k1 [BATCH * CDIM];                           // rowsum of K
__device__ float2 g_stats[BATCH * GRP];                          // (mean, rstd)

// ---------------- tf32 mma.sync micro-kernel ------------------------------
static __device__ __forceinline__ uint32_t to_tf32(float f) {
    uint32_t r;
    asm("cvt.rna.tf32.f32 %0, %1;" : "=r"(r) : "f"(f));
    return r;
}

static __device__ __forceinline__ void mma_tf32(float c[4], const uint4& a, const uint2& b) {
    asm volatile(
        "mma.sync.aligned.m16n8k8.row.col.f32.tf32.tf32.f32 "
        "{%0,%1,%2,%3}, {%4,%5,%6,%7}, {%8,%9}, {%0,%1,%2,%3};"
        : "+f"(c[0]), "+f"(c[1]), "+f"(c[2]), "+f"(c[3])
        : "r"(a.x), "r"(a.y), "r"(a.z), "r"(a.w), "r"(b.x), "r"(b.y));
}

// C[128,128] += A[128, NC*16] * B(k,n)[NC*16, 128] (tf32, fp32 acc).
// BK=16 double-buffered stages (8KB A + 8KB B per stage, 32KB total) so that
// 2 CTAs fit per SM (regs capped at 128 via __launch_bounds__(256,2)).
// A: row-major, lda stride, k contiguous.
// BMODE 0: B source is S[k][n] (ldb per k-row); GN = per-k affine from stats.
// BMODE 1: B source is S[col][k] (ldb per col, k contig); GN = per-thread
//          constant affine (scB, shB).
// SMEM fragment-permuted tf32 tiles:
//   As[((mtile*2+ks)*32 + g*4 + t)*4 + hi + 2*kh]   (2048 words / stage)
//   Bs[((ntile*2+ks)*32 + g*4 + t)*2 + kh]          (2048 words / stage)
template <int NC, int BMODE, bool GN>
static __device__ __forceinline__ void mma_block(
    const float* __restrict__ A, int lda,
    const float* __restrict__ B, int ldb,
    const float2* __restrict__ stats,
    const float* __restrict__ gamma, const float* __restrict__ beta,
    float scB, float shB,
    uint32_t* __restrict__ As, uint32_t* __restrict__ Bs,
    float C[2][8][4])
{
    const int tid = threadIdx.x;
    // A staging: row am (128 rows, 2 threads/row), 8-float half akq
    const int am  = tid >> 1, akq = (tid & 1) << 3;
    const int amt = am >> 4, ahi = (am >> 3) & 1, ag = am & 7;
    // B staging BMODE 0: row bk (16 rows, 16 threads/row), 8 n's at bnq
    const int bk  = tid >> 4, bnq = (tid & 15) << 3;
    // B staging BMODE 1: col bcl (128 cols, 2 threads/col), 8 k's at bkq
    const int bcl = tid >> 1, bkq = (tid & 1) << 3;
    const int lane = tid & 31, wid = tid >> 5;
    const int wm = wid & 3, wn = wid >> 2;

    float4 ra[2], rb[2];
    float sc = scB, sh = shB;

    // ---- prologue: load chunk 0 into regs ----
    {
        const float* pa = A + (size_t)am * lda + akq;
        ra[0] = *(const float4*)(pa);
        ra[1] = *(const float4*)(pa + 4);
        if (BMODE == 0) {
            if (GN) {
                float2 ms = stats[bk >> 3];
                sc = ms.y * gamma[bk];
                sh = fmaf(-ms.x, sc, beta[bk]);
            }
            const float* pb = B + (size_t)bk * ldb + bnq;
            #pragma unroll
            for (int q = 0; q < 2; q++) {
                float4 v = *(const float4*)(pb + q * 4);
                if (GN) {
                    v.x = fmaf(v.x, sc, sh); v.y = fmaf(v.y, sc, sh);
                    v.z = fmaf(v.z, sc, sh); v.w = fmaf(v.w, sc, sh);
                }
                rb[q] = v;
            }
        } else {
            const float* pb = B + (size_t)bcl * ldb + bkq;
            #pragma unroll
            for (int q = 0; q < 2; q++) {
                float4 v = *(const float4*)(pb + q * 4);
                if (GN) {
                    v.x = fmaf(v.x, sc, sh); v.y = fmaf(v.y, sc, sh);
                    v.z = fmaf(v.z, sc, sh); v.w = fmaf(v.w, sc, sh);
                }
                rb[q] = v;
            }
        }
    }

    #pragma unroll 1
    for (int i = 0; i < NC; i++) {
        uint32_t* Asb = As + (i & 1) * 2048;
        uint32_t* Bsb = Bs + (i & 1) * 2048;
        // ---- store regs -> SMEM stage (cvt to tf32, permuted layout) ----
        #pragma unroll
        for (int q = 0; q < 2; q++) {
            const int k = akq + q * 4, ks = k >> 3, kh = (k >> 2) & 1;
            const int base = ((amt * 2 + ks) * 32 + ag * 4) * 4 + ahi + 2 * kh;
            Asb[base + 0]  = to_tf32(ra[q].x);
            Asb[base + 4]  = to_tf32(ra[q].y);
            Asb[base + 8]  = to_tf32(ra[q].z);
            Asb[base + 12] = to_tf32(ra[q].w);
        }
        if (BMODE == 0) {
            const int t = bk & 3, ks = bk >> 3, kh = (bk >> 2) & 1;
            #pragma unroll
            for (int q = 0; q < 2; q++) {
                const int n = bnq + q * 4;
                const float v[4] = {rb[q].x, rb[q].y, rb[q].z, rb[q].w};
                #pragma unroll
                for (int j = 0; j < 4; j++) {
                    const int nn = n + j, g = nn & 7, nt = nn >> 3;
                    Bsb[((nt * 2 + ks) * 32 + g * 4 + t) * 2 + kh] = to_tf32(v[j]);
                }
            }
        } else {
            const int g = bcl & 7, nt = bcl >> 3;
            #pragma unroll
            for (int q = 0; q < 2; q++) {
                const int k = bkq + q * 4;
                const float v[4] = {rb[q].x, rb[q].y, rb[q].z, rb[q].w};
                #pragma unroll
                for (int j = 0; j < 4; j++) {
                    const int kk = k + j, ks = kk >> 3, kh = (kk >> 2) & 1, t = kk & 3;
                    Bsb[((nt * 2 + ks) * 32 + g * 4 + t) * 2 + kh] = to_tf32(v[j]);
                }
            }
        }
        __syncthreads();   // single sync per chunk (double-buffered stages)

        // ---- prefetch chunk i+1 into regs (overlaps with mma below) ----
        if (i + 1 < NC) {
            const float* pa = A + (i + 1) * 16 + (size_t)am * lda + akq;
            ra[0] = *(const float4*)(pa);
            ra[1] = *(const float4*)(pa + 4);
            if (BMODE == 0) {
                if (GN) {
                    const int c = (i + 1) * 16 + bk;
                    float2 ms = stats[c >> 3];
                    sc = ms.y * gamma[c];
                    sh = fmaf(-ms.x, sc, beta[c]);
                }
                const float* pb = B + (size_t)((i + 1) * 16 + bk) * ldb + bnq;
                #pragma unroll
                for (int q = 0; q < 2; q++) {
                    float4 v = *(const float4*)(pb + q * 4);
                    if (GN) {
                        v.x = fmaf(v.x, sc, sh); v.y = fmaf(v.y, sc, sh);
                        v.z = fmaf(v.z, sc, sh); v.w = fmaf(v.w, sc, sh);
                    }
                    rb[q] = v;
                }
            } else {
                const float* pb = B + (size_t)bcl * ldb + (i + 1) * 16 + bkq;
                #pragma unroll
                for (int q = 0; q < 2; q++) {
                    float4 v = *(const float4*)(pb + q * 4);
                    if (GN) {
                        v.x = fmaf(v.x, sc, sh); v.y = fmaf(v.y, sc, sh);
                        v.z = fmaf(v.z, sc, sh); v.w = fmaf(v.w, sc, sh);
                    }
                    rb[q] = v;
                }
            }
        }

        // ---- compute: 2 k-steps x (2 m-tiles x 8 n-tiles) mma ----
        #pragma unroll
        for (int ks = 0; ks < 2; ks++) {
            uint4 af[2];
            #pragma unroll
            for (int mt = 0; mt < 2; mt++)
                af[mt] = *(const uint4*)&Asb[(((wm * 2 + mt) * 2 + ks) * 32 + lane) * 4];
            uint2 bf[8];
            #pragma unroll
            for (int nt = 0; nt < 8; nt++)
                bf[nt] = *(const uint2*)&Bsb[(((wn * 8 + nt) * 2 + ks) * 32 + lane) * 2];
            #pragma unroll
            for (int mt = 0; mt < 2; mt++)
                #pragma unroll
                for (int nt = 0; nt < 8; nt++)
                    mma_tf32(C[mt][nt], af[mt], bf[nt]);
        }
    }
    __syncthreads();   // protect SMEM reuse by epilogues
}

// ---------------------------------------------------------------------------
// K1: GroupNorm statistics (one block per (b,g)) + zero g_k1 for this replay.
// ---------------------------------------------------------------------------
__global__ __launch_bounds__(256) void k_stats(const float* __restrict__ x) {
    const int bg = blockIdx.x;
    if (threadIdx.x < 8) g_k1[bg * 8 + threadIdx.x] = 0.f;
    const float4* p = reinterpret_cast<const float4*>(x + (size_t)bg * 8 * NDIM);
    float s = 0.f, s2 = 0.f;
    for (int i = threadIdx.x; i < 8 * NDIM / 4; i += 256) {
        float4 v = p[i];
        s  += v.x + v.y + v.z + v.w;
        s2 += v.x * v.x + v.y * v.y + v.z * v.z + v.w * v.w;
    }
    __shared__ float sh0[8], sh1[8];
    #pragma unroll
    for (int o = 16; o > 0; o >>= 1) {
        s  += __shfl_down_sync(0xffffffffu, s,  o);
        s2 += __shfl_down_sync(0xffffffffu, s2, o);
    }
    const int lane = threadIdx.x & 31, w = threadIdx.x >> 5;
    if (lane == 0) { sh0[w] = s; sh1[w] = s2; }
    __syncthreads();
    if (w == 0) {
        s  = (lane < 8) ? sh0[lane] : 0.f;
        s2 = (lane < 8) ? sh1[lane] : 0.f;
        #pragma unroll
        for (int o = 4; o > 0; o >>= 1) {
            s  += __shfl_down_sync(0xffffffffu, s,  o);
            s2 += __shfl_down_sync(0xffffffffu, s2, o);
        }
        if (lane == 0) {
            const float inv = 1.f / (8.f * NDIM);
            float mean = s * inv;
            float var  = s2 * inv - mean * mean;
            g_stats[bg] = make_float2(mean, rsqrtf(var + 1e-6f));
        }
    }
}

// ---------------------------------------------------------------------------
// K2: Q,K = W_{q,k} @ GN(x) via tf32 mma.sync (GN folded into B staging).
// bias + elu+1 epilogue; K path also accumulates k1 rowsums (atomicAdd).
// ---------------------------------------------------------------------------
__global__ __launch_bounds__(256, 2) void k_qkv_t(
    const float* __restrict__ x,
    const float* __restrict__ wq, const float* __restrict__ bq,
    const float* __restrict__ wk, const float* __restrict__ bk,
    const float* __restrict__ gamma, const float* __restrict__ beta)
{
    extern __shared__ uint32_t smp[];
    uint32_t* As = smp;            // 2 x 2048
    uint32_t* Bs = smp + 4096;     // 2 x 2048
    const int b  = blockIdx.z;
    const int by = blockIdx.y;            // 0..3
    const int which = by >> 1;            // 0=q 1=k
    const int m0 = (by & 1) * 128;
    const int n0 = blockIdx.x * 128;
    const float* W    = which == 0 ? wq : wk;
    const float* bias = which == 0 ? bq : bk;

    float C[2][8][4];
    #pragma unroll
    for (int mt = 0; mt < 2; mt++)
        #pragma unroll
        for (int nt = 0; nt < 8; nt++)
            #pragma unroll
            for (int r = 0; r < 4; r++) C[mt][nt][r] = 0.f;

    mma_block<16, 0, true>(W + (size_t)m0 * CDIM, CDIM,
                           x + (size_t)b * CDIM * NDIM + n0, NDIM,
                           g_stats + b * GRP, gamma, beta, 1.f, 0.f, As, Bs, C);

    const int lane = threadIdx.x & 31, wid = threadIdx.x >> 5;
    const int g = lane >> 2, t = lane & 3, wm = wid & 3, wn = wid >> 2;
    float* outp = g_qkv + (((size_t)b * 2 + which) * CDIM + m0) * NDIM + n0;
    float rs0[2] = {0.f, 0.f}, rs1[2] = {0.f, 0.f};
    #pragma unroll
    for (int mt = 0; mt < 2; mt++) {
        const int r0 = wm * 32 + mt * 16 + g;
        const float b0v = bias[m0 + r0], b1v = bias[m0 + r0 + 8];
        #pragma unroll
        for (int nt = 0; nt < 8; nt++) {
            const int col = wn * 64 + nt * 8 + 2 * t;
            float v0 = C[mt][nt][0] + b0v, v1 = C[mt][nt][1] + b0v;
            float v2 = C[mt][nt][2] + b1v, v3 = C[mt][nt][3] + b1v;
            v0 = (v0 > 0.f) ? (v0 + 1.f) : expf(v0);   // elu+1
            v1 = (v1 > 0.f) ? (v1 + 1.f) : expf(v1);
            v2 = (v2 > 0.f) ? (v2 + 1.f) : expf(v2);
            v3 = (v3 > 0.f) ? (v3 + 1.f) : expf(v3);
            rs0[mt] += v0 + v1;
            rs1[mt] += v2 + v3;
            *(float2*)(outp + (size_t)r0 * NDIM + col)       = make_float2(v0, v1);
            *(float2*)(outp + (size_t)(r0 + 8) * NDIM + col) = make_float2(v2, v3);
        }
    }
    if (which == 1) {   // k1[c] = sum_n K[c,n]
        #pragma unroll
        for (int mt = 0; mt < 2; mt++) {
            float a = rs0[mt], c2 = rs1[mt];
            a  += __shfl_xor_sync(0xffffffffu, a,  1);
            a  += __shfl_xor_sync(0xffffffffu, a,  2);
            c2 += __shfl_xor_sync(0xffffffffu, c2, 1);
            c2 += __shfl_xor_sync(0xffffffffu, c2, 2);
            if (t == 0) {
                const int r0 = wm * 32 + mt * 16 + g;
                atomicAdd(&g_k1[b * CDIM + m0 + r0], a);
                atomicAdd(&g_k1[b * CDIM + m0 + r0 + 8], c2);
            }
        }
    }
}

// ---------------------------------------------------------------------------
// K3: S partials. Sp[sp][b][c][e] = sum_{n in split} K[c,n] * GN(x)[e,n].
// GN fold is a per-thread constant (row e fixed per staging thread).
// ---------------------------------------------------------------------------
__global__ __launch_bounds__(256, 2) void k_S(const float* __restrict__ x,
                                              const float* __restrict__ gamma,
                                              const float* __restrict__ beta) {
    extern __shared__ uint32_t smp[];
    uint32_t* As = smp;
    uint32_t* Bs = smp + 4096;
    const int z = blockIdx.z;
    const int b = z / KVSPLIT, sp = z % KVSPLIT;
    const int c0 = blockIdx.y * 128, e0 = blockIdx.x * 128;
    const int nb = sp * (NDIM / KVSPLIT);
    const float* Kf = g_qkv + ((size_t)b * 2 + 1) * CDIM * NDIM;

    const int e = e0 + (threadIdx.x >> 1);     // staging row for BMODE 1
    float2 ms = g_stats[b * GRP + (e >> 3)];
    const float sc = ms.y * gamma[e];
    const float sh = fmaf(-ms.x, sc, beta[e]);

    float C[2][8][4];
    #pragma unroll
    for (int mt = 0; mt < 2; mt++)
        #pragma unroll
        for (int nt = 0; nt < 8; nt++)
            #pragma unroll
            for (int r = 0; r < 4; r++) C[mt][nt][r] = 0.f;

    mma_block<(NDIM / KVSPLIT) / 16, 1, true>(
        Kf + (size_t)c0 * NDIM + nb, NDIM,
        x + ((size_t)b * CDIM + e0) * NDIM + nb, NDIM,
        nullptr, nullptr, nullptr, sc, sh, As, Bs, C);

    const int lane = threadIdx.x & 31, wid = threadIdx.x >> 5;
    const int g = lane >> 2, t = lane & 3, wm = wid & 3, wn = wid >> 2;
    float* dst = g_Sp + ((size_t)sp * BATCH + b) * CDIM * CDIM;
    #pragma unroll
    for (int mt = 0; mt < 2; mt++) {
        const int r0 = c0 + wm * 32 + mt * 16 + g;
        #pragma unroll
        for (int nt = 0; nt < 8; nt++) {
            const int col = e0 + wn * 64 + nt * 8 + 2 * t;
            *(float2*)(dst + (size_t)r0 * CDIM + col)       = make_float2(C[mt][nt][0], C[mt][nt][1]);
            *(float2*)(dst + (size_t)(r0 + 8) * CDIM + col) = make_float2(C[mt][nt][2], C[mt][nt][3]);
        }
    }
}

// ---------------------------------------------------------------------------
// K4: streaming reduction of the 8 S partials.
// ---------------------------------------------------------------------------
__global__ __launch_bounds__(256) void k_red() {
    const size_t i = (size_t)blockIdx.x * 256 + threadIdx.x;   // float4 idx
    const size_t SS = (size_t)BATCH * CDIM * CDIM / 4;
    const float4* p = reinterpret_cast<const float4*>(g_Sp);
    float4 a = p[i];
    #pragma unroll
    for (int s = 1; s < KVSPLIT; s++) {
        float4 v = p[i + (size_t)s * SS];
        a.x += v.x; a.y += v.y; a.z += v.z; a.w += v.w;
    }
    reinterpret_cast<float4*>(g_S)[i] = a;
}

// ---------------------------------------------------------------------------
// K5: U = wo @ Wv (batch-independent) and wt = wo @ bv. fp32, tiny.
// ---------------------------------------------------------------------------
__global__ __launch_bounds__(256) void k_prep(const float* __restrict__ wo,
                                              const float* __restrict__ wv,
                                              const float* __restrict__ bv) {
    const int o0 = blockIdx.y * 64, e0 = blockIdx.x * 64;
    const int tid = threadIdx.x;
    if (blockIdx.x == 0 && tid < 64) {        // wt for this o-range
        const float* wr = wo + (size_t)(o0 + tid) * CDIM;
        float s = 0.f;
        for (int d = 0; d < CDIM; d += 4) {
            float4 w4 = *(const float4*)(wr + d);
            float4 b4 = *(const float4*)(bv + d);
            s += w4.x * b4.x + w4.y * b4.y + w4.z * b4.z + w4.w * b4.w;
        }
        g_wt[o0 + tid] = s;
    }

    __shared__ float As[16][64];
    __shared__ float Bs[16][64];
    const int arow = tid >> 2, acol = (tid & 3) << 2;   // A^T staging
    const int brow = tid >> 4, bcol = (tid & 15) << 2;  // B row-major staging
    const int tx = (tid & 15) << 2, ty = (tid >> 4) << 2;

    float acc[4][4];
    #pragma unroll
    for (int i = 0; i < 4; i++)
        #pragma unroll
        for (int j = 0; j < 4; j++) acc[i][j] = 0.f;

    for (int k0 = 0; k0 < CDIM; k0 += 16) {
        float4 av = *(const float4*)(wo + (size_t)(o0 + arow) * CDIM + k0 + acol);
        As[acol + 0][arow] = av.x; As[acol + 1][arow] = av.y;
        As[acol + 2][arow] = av.z; As[acol + 3][arow] = av.w;
        *(float4*)&Bs[brow][bcol] =
            *(const float4*)(wv + (size_t)(k0 + brow) * CDIM + e0 + bcol);
        __syncthreads();
        #pragma unroll
        for (int k = 0; k < 16; k++) {
            float4 a4 = *(const float4*)&As[k][ty];
            float4 b4 = *(const float4*)&Bs[k][tx];
            float a[4] = {a4.x, a4.y, a4.z, a4.w};
            float bb[4] = {b4.x, b4.y, b4.z, b4.w};
            #pragma unroll
            for (int i = 0; i < 4; i++)
                #pragma unroll
                for (int j = 0; j < 4; j++)
                    acc[i][j] = fmaf(a[i], bb[j], acc[i][j]);
        }
        __syncthreads();
    }
    #pragma unroll
    for (int i = 0; i < 4; i++)
        *(float4*)(g_U + (size_t)(o0 + ty + i) * CDIM + e0 + tx) =
            make_float4(acc[i][0], acc[i][1], acc[i][2], acc[i][3]);
}

// ---------------------------------------------------------------------------
// K6: M[b][o][c] = sum_e U[o,e] S[b][c,e] + wt[o] * k1[b][c]. fp32, tiny.
// ---------------------------------------------------------------------------
__global__ __launch_bounds__(256) void k_M() {
    const int b  = blockIdx.z;
    const int o0 = blockIdx.y * 64, c0 = blockIdx.x * 64;
    const float* Sb = g_S + (size_t)b * CDIM * CDIM;

    __shared__ float As[16][64];
    __shared__ float Bs[16][64];
    const int tid  = threadIdx.x;
    const int arow = tid >> 2, acol = (tid & 3) << 2;
    const int tx = (tid & 15) << 2, ty = (tid >> 4) << 2;

    float acc[4][4];
    #pragma unroll
    for (int i = 0; i < 4; i++)
        #pragma unroll
        for (int j = 0; j < 4; j++) acc[i][j] = 0.f;

    for (int k0 = 0; k0 < CDIM; k0 += 16) {
        float4 av = *(const float4*)(g_U + (size_t)(o0 + arow) * CDIM + k0 + acol);
        As[acol + 0][arow] = av.x; As[acol + 1][arow] = av.y;
        As[acol + 2][arow] = av.z; As[acol + 3][arow] = av.w;
        float4 bv = *(const float4*)(Sb + (size_t)(c0 + arow) * CDIM + k0 + acol);
        Bs[acol + 0][arow] = bv.x; Bs[acol + 1][arow] = bv.y;
        Bs[acol + 2][arow] = bv.z; Bs[acol + 3][arow] = bv.w;
        __syncthreads();
        #pragma unroll
        for (int k = 0; k < 16; k++) {
            float4 a4 = *(const float4*)&As[k][ty];
            float4 b4 = *(const float4*)&Bs[k][tx];
            float a[4] = {a4.x, a4.y, a4.z, a4.w};
            float bb[4] = {b4.x, b4.y, b4.z, b4.w};
            #pragma unroll
            for (int i = 0; i < 4; i++)
                #pragma unroll
                for (int j = 0; j < 4; j++)
                    acc[i][j] = fmaf(a[i], bb[j], acc[i][j]);
        }
        __syncthreads();
    }
    float* Mb = g_M + (size_t)b * CDIM * CDIM;
    const float* k1b = g_k1 + b * CDIM;
    #pragma unroll
    for (int i = 0; i < 4; i++) {
        const float w = g_wt[o0 + ty + i];
        *(float4*)(Mb + (size_t)(o0 + ty + i) * CDIM + c0 + tx) = make_float4(
            acc[i][0] + w * k1b[c0 + tx + 0], acc[i][1] + w * k1b[c0 + tx + 1],
            acc[i][2] + w * k1b[c0 + tx + 2], acc[i][3] + w * k1b[c0 + tx + 3]);
    }
}

// ---------------------------------------------------------------------------
// K7: out[b][o][n] = x[b][o][n] + M[b][o,:] . Q[:,n] + bo[o].
// ---------------------------------------------------------------------------
__global__ __launch_bounds__(256, 2) void k_out_t(const float* __restrict__ x,
                                                  const float* __restrict__ bo,
                                                  float* __restrict__ out) {
    extern __shared__ uint32_t smp[];
    uint32_t* As = smp;
    uint32_t* Bs = smp + 4096;
    const int b  = blockIdx.z;
    const int o0 = blockIdx.y * 128, n0 = blockIdx.x * 128;
    const float* Mb = g_M + (size_t)b * CDIM * CDIM;
    const float* Qf = g_qkv + (size_t)b * 2 * CDIM * NDIM;   // q plane [c][n]

    float C[2][8][4];
    #pragma unroll
    for (int mt = 0; mt < 2; mt++)
        #pragma unroll
        for (int nt = 0; nt < 8; nt++)
            #pragma unroll
            for (int r = 0; r < 4; r++) C[mt][nt][r] = 0.f;

    mma_block<16, 0, false>(Mb + (size_t)o0 * CDIM, CDIM,
                            Qf + n0, NDIM,
                            nullptr, nullptr, nullptr, 1.f, 0.f, As, Bs, C);

    const int lane = threadIdx.x & 31, wid = threadIdx.x >> 5;
    const int g = lane >> 2, t = lane & 3, wm = wid & 3, wn = wid >> 2;
    const float* xb = x   + ((size_t)b * CDIM + o0) * NDIM + n0;
    float*       ob = out + ((size_t)b * CDIM + o0) * NDIM + n0;
    #pragma unroll
    for (int mt = 0; mt < 2; mt++) {
        const int r0 = wm * 32 + mt * 16 + g;
        const float b0v = bo[o0 + r0], b1v = bo[o0 + r0 + 8];
        #pragma unroll
        for (int nt = 0; nt < 8; nt++) {
            const int col = wn * 64 + nt * 8 + 2 * t;
            float2 x0 = *(const float2*)(xb + (size_t)r0 * NDIM + col);
            float2 x1 = *(const float2*)(xb + (size_t)(r0 + 8) * NDIM + col);
            *(float2*)(ob + (size_t)r0 * NDIM + col) =
                make_float2(C[mt][nt][0] + b0v + x0.x, C[mt][nt][1] + b0v + x0.y);
            *(float2*)(ob + (size_t)(r0 + 8) * NDIM + col) =
                make_float2(C[mt][nt][2] + b1v + x1.x, C[mt][nt][3] + b1v + x1.y);
        }
    }
}

// ---------------------------------------------------------------------------
#define MMA_SMEM 32768
extern "C" void kernel_launch(void* const* d_in, const int* in_sizes, int n_in,
                              void* d_out, int out_size) {
    const float* x     = (const float*)d_in[0];
    const float* gamma = (const float*)d_in[1];
    const float* beta  = (const float*)d_in[2];
    const float* wq    = (const float*)d_in[3];
    const float* bq    = (const float*)d_in[4];
    const float* wk    = (const float*)d_in[5];
    const float* bk    = (const float*)d_in[6];
    const float* wv    = (const float*)d_in[7];
    const float* bv    = (const float*)d_in[8];
    const float* wo    = (const float*)d_in[9];
    const float* bo    = (const float*)d_in[10];
    float* out = (float*)d_out;

    cudaFuncSetAttribute(k_qkv_t, cudaFuncAttributeMaxDynamicSharedMemorySize, MMA_SMEM);
    cudaFuncSetAttribute(k_S,     cudaFuncAttributeMaxDynamicSharedMemorySize, MMA_SMEM);
    cudaFuncSetAttribute(k_out_t, cudaFuncAttributeMaxDynamicSharedMemorySize, MMA_SMEM);

    k_stats<<<BATCH * GRP, 256>>>(x);
    k_prep<<<dim3(4, 4), 256>>>(wo, wv, bv);
    k_qkv_t<<<dim3(NDIM / 128, 4, BATCH), 256, MMA_SMEM>>>(x, wq, bq, wk, bk, gamma, beta);
    k_S<<<dim3(2, 2, BATCH * KVSPLIT), 256, MMA_SMEM>>>(x, gamma, beta);
    k_red<<<(BATCH * CDIM * CDIM) / (256 * 4), 256>>>();
    k_M<<<dim3(4, 4, BATCH), 256>>>();
    k_out_t<<<dim3(NDIM / 128, 2, BATCH), 256, MMA_SMEM>>>(x, bo, out);
}

// round 11
// speedup vs baseline: 1.2670x; 1.2670x over previous
#include <cuda_runtime.h>
#include <math.h>
#include <stdint.h>

// Problem dims (LinearAttnBlock: B=8, C=256, H=W=64)
#define BATCH 8
#define CDIM  256
#define NDIM  4096
#define GRP   32
#define KVSPLIT 8

// ---------------- scratch (__device__ globals; no allocation allowed) ------
__device__ float  g_qkv[(size_t)BATCH * 2 * CDIM * NDIM];        // [b][q/k][c][n]
__device__ float  g_Sp [(size_t)KVSPLIT * BATCH * CDIM * CDIM];  // S split partials
__device__ float  g_S  [BATCH * CDIM * CDIM];                    // [b][c][e] = K.h^T
__device__ float  g_M  [BATCH * CDIM * CDIM];                    // [b][o][c]
__device__ float  g_U  [CDIM * CDIM];                            // wo @ Wv
__device__ float  g_wt [CDIM];                                   // wo @ bv
__device__ float  g_k1 [BATCH * CDIM];                           // rowsum of K
__device__ float2 g_stats[BATCH * GRP];                          // (mean, rstd)

// ---------------- tf32 mma.sync micro-kernel ------------------------------
static __device__ __forceinline__ uint32_t to_tf32(float f) {
    uint32_t r;
    asm("cvt.rna.tf32.f32 %0, %1;" : "=r"(r) : "f"(f));
    return r;
}

static __device__ __forceinline__ void mma_tf32(float c[4], const uint4& a, const uint2& b) {
    asm volatile(
        "mma.sync.aligned.m16n8k8.row.col.f32.tf32.tf32.f32 "
        "{%0,%1,%2,%3}, {%4,%5,%6,%7}, {%8,%9}, {%0,%1,%2,%3};"
        : "+f"(c[0]), "+f"(c[1]), "+f"(c[2]), "+f"(c[3])
        : "r"(a.x), "r"(a.y), "r"(a.z), "r"(a.w), "r"(b.x), "r"(b.y));
}

// C[128,128] += A[128, NC*16] * B(k,n)[NC*16, 128] (tf32, fp32 acc).
// BK=16 double-buffered stages; 2 CTAs/SM via __launch_bounds__(256,2).
// SMEM fragment-permuted tf32 tiles with XOR bank swizzle:
//   A word idx = ((mt2*2+ks)*32 + ag*4 + t)*4 + ahi + 2*kh,  idx ^= ((ag>>1)&3)<<2
//   B word idx = ((nt*2+ks)*32 + g*4 + t)*2 + kh,            idx ^= (nt&15)<<1
// The XOR de-conflicts the staging stores (were 8-way / 16-way) while the
// frag loads (lds.128 / lds.64) stay conflict-free (constant XOR per instr).
template <int NC, int BMODE, bool GN>
static __device__ __forceinline__ void mma_block(
    const float* __restrict__ A, int lda,
    const float* __restrict__ B, int ldb,
    const float2* __restrict__ stats,
    const float* __restrict__ gamma, const float* __restrict__ beta,
    float scB, float shB,
    uint32_t* __restrict__ As, uint32_t* __restrict__ Bs,
    float C[2][8][4])
{
    const int tid = threadIdx.x;
    // A staging: row am (128 rows, 2 threads/row), 8-float half akq
    const int am  = tid >> 1, akq = (tid & 1) << 3;
    const int amt = am >> 4, ahi = (am >> 3) & 1, ag = am & 7;
    const int axor = ((ag >> 1) & 3) << 2;            // A store/load swizzle
    // B staging BMODE 0: row bk (16 rows, 16 threads/row), 8 n's at bnq
    const int bk  = tid >> 4, bnq = (tid & 15) << 3;
    // B staging BMODE 1: col bcl (128 cols, 2 threads/col), 8 k's at bkq
    const int bcl = tid >> 1, bkq = (tid & 1) << 3;
    const int lane = tid & 31, wid = tid >> 5;
    const int wm = wid & 3, wn = wid >> 2;

    float4 ra[2], rb[2];
    float sc = scB, sh = shB;

    // ---- prologue: load chunk 0 into regs ----
    {
        const float* pa = A + (size_t)am * lda + akq;
        ra[0] = *(const float4*)(pa);
        ra[1] = *(const float4*)(pa + 4);
        if (BMODE == 0) {
            if (GN) {
                float2 ms = stats[bk >> 3];
                sc = ms.y * gamma[bk];
                sh = fmaf(-ms.x, sc, beta[bk]);
            }
            const float* pb = B + (size_t)bk * ldb + bnq;
            #pragma unroll
            for (int q = 0; q < 2; q++) {
                float4 v = *(const float4*)(pb + q * 4);
                if (GN) {
                    v.x = fmaf(v.x, sc, sh); v.y = fmaf(v.y, sc, sh);
                    v.z = fmaf(v.z, sc, sh); v.w = fmaf(v.w, sc, sh);
                }
                rb[q] = v;
            }
        } else {
            const float* pb = B + (size_t)bcl * ldb + bkq;
            #pragma unroll
            for (int q = 0; q < 2; q++) {
                float4 v = *(const float4*)(pb + q * 4);
                if (GN) {
                    v.x = fmaf(v.x, sc, sh); v.y = fmaf(v.y, sc, sh);
                    v.z = fmaf(v.z, sc, sh); v.w = fmaf(v.w, sc, sh);
                }
                rb[q] = v;
            }
        }
    }

    #pragma unroll 1
    for (int i = 0; i < NC; i++) {
        uint32_t* Asb = As + (i & 1) * 2048;
        uint32_t* Bsb = Bs + (i & 1) * 2048;
        // ---- store regs -> SMEM stage (cvt to tf32, swizzled layout) ----
        #pragma unroll
        for (int q = 0; q < 2; q++) {
            const int k = akq + q * 4, ks = k >> 3, kh = (k >> 2) & 1;
            const int base = ((amt * 2 + ks) * 32 + ag * 4) * 4 + ahi + 2 * kh;
            Asb[(base + 0)  ^ axor] = to_tf32(ra[q].x);
            Asb[(base + 4)  ^ axor] = to_tf32(ra[q].y);
            Asb[(base + 8)  ^ axor] = to_tf32(ra[q].z);
            Asb[(base + 12) ^ axor] = to_tf32(ra[q].w);
        }
        if (BMODE == 0) {
            const int t = bk & 3, ks = bk >> 3, kh = (bk >> 2) & 1;
            #pragma unroll
            for (int q = 0; q < 2; q++) {
                const int n = bnq + q * 4;
                const float v[4] = {rb[q].x, rb[q].y, rb[q].z, rb[q].w};
                #pragma unroll
                for (int j = 0; j < 4; j++) {
                    const int nn = n + j, g = nn & 7, nt = nn >> 3;
                    const int idx = ((nt * 2 + ks) * 32 + g * 4 + t) * 2 + kh;
                    Bsb[idx ^ ((nt & 15) << 1)] = to_tf32(v[j]);
                }
            }
        } else {
            const int g = bcl & 7, nt = bcl >> 3;
            const int bxor = (nt & 15) << 1;
            #pragma unroll
            for (int q = 0; q < 2; q++) {
                const int k = bkq + q * 4;
                const float v[4] = {rb[q].x, rb[q].y, rb[q].z, rb[q].w};
                #pragma unroll
                for (int j = 0; j < 4; j++) {
                    const int kk = k + j, ks = kk >> 3, kh = (kk >> 2) & 1, t = kk & 3;
                    const int idx = ((nt * 2 + ks) * 32 + g * 4 + t) * 2 + kh;
                    Bsb[idx ^ bxor] = to_tf32(v[j]);
                }
            }
        }
        __syncthreads();   // single sync per chunk (double-buffered stages)

        // ---- prefetch chunk i+1 into regs (overlaps with mma below) ----
        if (i + 1 < NC) {
            const float* pa = A + (i + 1) * 16 + (size_t)am * lda + akq;
            ra[0] = *(const float4*)(pa);
            ra[1] = *(const float4*)(pa + 4);
            if (BMODE == 0) {
                if (GN) {
                    const int c = (i + 1) * 16 + bk;
                    float2 ms = stats[c >> 3];
                    sc = ms.y * gamma[c];
                    sh = fmaf(-ms.x, sc, beta[c]);
                }
                const float* pb = B + (size_t)((i + 1) * 16 + bk) * ldb + bnq;
                #pragma unroll
                for (int q = 0; q < 2; q++) {
                    float4 v = *(const float4*)(pb + q * 4);
                    if (GN) {
                        v.x = fmaf(v.x, sc, sh); v.y = fmaf(v.y, sc, sh);
                        v.z = fmaf(v.z, sc, sh); v.w = fmaf(v.w, sc, sh);
                    }
                    rb[q] = v;
                }
            } else {
                const float* pb = B + (size_t)bcl * ldb + (i + 1) * 16 + bkq;
                #pragma unroll
                for (int q = 0; q < 2; q++) {
                    float4 v = *(const float4*)(pb + q * 4);
                    if (GN) {
                        v.x = fmaf(v.x, sc, sh); v.y = fmaf(v.y, sc, sh);
                        v.z = fmaf(v.z, sc, sh); v.w = fmaf(v.w, sc, sh);
                    }
                    rb[q] = v;
                }
            }
        }

        // ---- compute: 2 k-steps x (2 m-tiles x 8 n-tiles) mma ----
        #pragma unroll
        for (int ks = 0; ks < 2; ks++) {
            uint4 af[2];
            #pragma unroll
            for (int mt = 0; mt < 2; mt++)
                af[mt] = *(const uint4*)&Asb[
                    ((((wm * 2 + mt) * 2 + ks) * 32 + lane) * 4) ^ (((lane >> 3) & 3) << 2)];
            uint2 bf[8];
            #pragma unroll
            for (int nt = 0; nt < 8; nt++) {
                const int NT = wn * 8 + nt;
                bf[nt] = *(const uint2*)&Bsb[
                    (((NT * 2 + ks) * 32 + lane) * 2) ^ ((NT & 15) << 1)];
            }
            #pragma unroll
            for (int mt = 0; mt < 2; mt++)
                #pragma unroll
                for (int nt = 0; nt < 8; nt++)
                    mma_tf32(C[mt][nt], af[mt], bf[nt]);
        }
    }
    __syncthreads();   // protect SMEM reuse by epilogues
}

// ---------------------------------------------------------------------------
// K1: GroupNorm statistics (one block per (b,g)) + zero g_k1 for this replay.
// ---------------------------------------------------------------------------
__global__ __launch_bounds__(256) void k_stats(const float* __restrict__ x) {
    const int bg = blockIdx.x;
    if (threadIdx.x < 8) g_k1[bg * 8 + threadIdx.x] = 0.f;
    const float4* p = reinterpret_cast<const float4*>(x + (size_t)bg * 8 * NDIM);
    float s = 0.f, s2 = 0.f;
    for (int i = threadIdx.x; i < 8 * NDIM / 4; i += 256) {
        float4 v = p[i];
        s  += v.x + v.y + v.z + v.w;
        s2 += v.x * v.x + v.y * v.y + v.z * v.z + v.w * v.w;
    }
    __shared__ float sh0[8], sh1[8];
    #pragma unroll
    for (int o = 16; o > 0; o >>= 1) {
        s  += __shfl_down_sync(0xffffffffu, s,  o);
        s2 += __shfl_down_sync(0xffffffffu, s2, o);
    }
    const int lane = threadIdx.x & 31, w = threadIdx.x >> 5;
    if (lane == 0) { sh0[w] = s; sh1[w] = s2; }
    __syncthreads();
    if (w == 0) {
        s  = (lane < 8) ? sh0[lane] : 0.f;
        s2 = (lane < 8) ? sh1[lane] : 0.f;
        #pragma unroll
        for (int o = 4; o > 0; o >>= 1) {
            s  += __shfl_down_sync(0xffffffffu, s,  o);
            s2 += __shfl_down_sync(0xffffffffu, s2, o);
        }
        if (lane == 0) {
            const float inv = 1.f / (8.f * NDIM);
            float mean = s * inv;
            float var  = s2 * inv - mean * mean;
            g_stats[bg] = make_float2(mean, rsqrtf(var + 1e-6f));
        }
    }
}

// ---------------------------------------------------------------------------
// K2: Q,K = W_{q,k} @ GN(x) via tf32 mma.sync (GN folded into B staging).
// bias + elu+1 epilogue; K path also accumulates k1 rowsums (atomicAdd).
// ---------------------------------------------------------------------------
__global__ __launch_bounds__(256, 2) void k_qkv_t(
    const float* __restrict__ x,
    const float* __restrict__ wq, const float* __restrict__ bq,
    const float* __restrict__ wk, const float* __restrict__ bk,
    const float* __restrict__ gamma, const float* __restrict__ beta)
{
    extern __shared__ uint32_t smp[];
    uint32_t* As = smp;            // 2 x 2048
    uint32_t* Bs = smp + 4096;     // 2 x 2048
    const int b  = blockIdx.z;
    const int by = blockIdx.y;            // 0..3
    const int which = by >> 1;            // 0=q 1=k
    const int m0 = (by & 1) * 128;
    const int n0 = blockIdx.x * 128;
    const float* W    = which == 0 ? wq : wk;
    const float* bias = which == 0 ? bq : bk;

    float C[2][8][4];
    #pragma unroll
    for (int mt = 0; mt < 2; mt++)
        #pragma unroll
        for (int nt = 0; nt < 8; nt++)
            #pragma unroll
            for (int r = 0; r < 4; r++) C[mt][nt][r] = 0.f;

    mma_block<16, 0, true>(W + (size_t)m0 * CDIM, CDIM,
                           x + (size_t)b * CDIM * NDIM + n0, NDIM,
                           g_stats + b * GRP, gamma, beta, 1.f, 0.f, As, Bs, C);

    const int lane = threadIdx.x & 31, wid = threadIdx.x >> 5;
    const int g = lane >> 2, t = lane & 3, wm = wid & 3, wn = wid >> 2;
    float* outp = g_qkv + (((size_t)b * 2 + which) * CDIM + m0) * NDIM + n0;
    float rs0[2] = {0.f, 0.f}, rs1[2] = {0.f, 0.f};
    #pragma unroll
    for (int mt = 0; mt < 2; mt++) {
        const int r0 = wm * 32 + mt * 16 + g;
        const float b0v = bias[m0 + r0], b1v = bias[m0 + r0 + 8];
        #pragma unroll
        for (int nt = 0; nt < 8; nt++) {
            const int col = wn * 64 + nt * 8 + 2 * t;
            float v0 = C[mt][nt][0] + b0v, v1 = C[mt][nt][1] + b0v;
            float v2 = C[mt][nt][2] + b1v, v3 = C[mt][nt][3] + b1v;
            v0 = (v0 > 0.f) ? (v0 + 1.f) : expf(v0);   // elu+1
            v1 = (v1 > 0.f) ? (v1 + 1.f) : expf(v1);
            v2 = (v2 > 0.f) ? (v2 + 1.f) : expf(v2);
            v3 = (v3 > 0.f) ? (v3 + 1.f) : expf(v3);
            rs0[mt] += v0 + v1;
            rs1[mt] += v2 + v3;
            *(float2*)(outp + (size_t)r0 * NDIM + col)       = make_float2(v0, v1);
            *(float2*)(outp + (size_t)(r0 + 8) * NDIM + col) = make_float2(v2, v3);
        }
    }
    if (which == 1) {   // k1[c] = sum_n K[c,n]
        #pragma unroll
        for (int mt = 0; mt < 2; mt++) {
            float a = rs0[mt], c2 = rs1[mt];
            a  += __shfl_xor_sync(0xffffffffu, a,  1);
            a  += __shfl_xor_sync(0xffffffffu, a,  2);
            c2 += __shfl_xor_sync(0xffffffffu, c2, 1);
            c2 += __shfl_xor_sync(0xffffffffu, c2, 2);
            if (t == 0) {
                const int r0 = wm * 32 + mt * 16 + g;
                atomicAdd(&g_k1[b * CDIM + m0 + r0], a);
                atomicAdd(&g_k1[b * CDIM + m0 + r0 + 8], c2);
            }
        }
    }
}

// ---------------------------------------------------------------------------
// K3: S partials. Sp[sp][b][c][e] = sum_{n in split} K[c,n] * GN(x)[e,n].
// GN fold is a per-thread constant (row e fixed per staging thread).
// ---------------------------------------------------------------------------
__global__ __launch_bounds__(256, 2) void k_S(const float* __restrict__ x,
                                              const float* __restrict__ gamma,
                                              const float* __restrict__ beta) {
    extern __shared__ uint32_t smp[];
    uint32_t* As = smp;
    uint32_t* Bs = smp + 4096;
    const int z = blockIdx.z;
    const int b = z / KVSPLIT, sp = z % KVSPLIT;
    const int c0 = blockIdx.y * 128, e0 = blockIdx.x * 128;
    const int nb = sp * (NDIM / KVSPLIT);
    const float* Kf = g_qkv + ((size_t)b * 2 + 1) * CDIM * NDIM;

    const int e = e0 + (threadIdx.x >> 1);     // staging row for BMODE 1
    float2 ms = g_stats[b * GRP + (e >> 3)];
    const float sc = ms.y * gamma[e];
    const float sh = fmaf(-ms.x, sc, beta[e]);

    float C[2][8][4];
    #pragma unroll
    for (int mt = 0; mt < 2; mt++)
        #pragma unroll
        for (int nt = 0; nt < 8; nt++)
            #pragma unroll
            for (int r = 0; r < 4; r++) C[mt][nt][r] = 0.f;

    mma_block<(NDIM / KVSPLIT) / 16, 1, true>(
        Kf + (size_t)c0 * NDIM + nb, NDIM,
        x + ((size_t)b * CDIM + e0) * NDIM + nb, NDIM,
        nullptr, nullptr, nullptr, sc, sh, As, Bs, C);

    const int lane = threadIdx.x & 31, wid = threadIdx.x >> 5;
    const int g = lane >> 2, t = lane & 3, wm = wid & 3, wn = wid >> 2;
    float* dst = g_Sp + ((size_t)sp * BATCH + b) * CDIM * CDIM;
    #pragma unroll
    for (int mt = 0; mt < 2; mt++) {
        const int r0 = c0 + wm * 32 + mt * 16 + g;
        #pragma unroll
        for (int nt = 0; nt < 8; nt++) {
            const int col = e0 + wn * 64 + nt * 8 + 2 * t;
            *(float2*)(dst + (size_t)r0 * CDIM + col)       = make_float2(C[mt][nt][0], C[mt][nt][1]);
            *(float2*)(dst + (size_t)(r0 + 8) * CDIM + col) = make_float2(C[mt][nt][2], C[mt][nt][3]);
        }
    }
}

// ---------------------------------------------------------------------------
// K4: streaming reduction of the 8 S partials.
// ---------------------------------------------------------------------------
__global__ __launch_bounds__(256) void k_red() {
    const size_t i = (size_t)blockIdx.x * 256 + threadIdx.x;   // float4 idx
    const size_t SS = (size_t)BATCH * CDIM * CDIM / 4;
    const float4* p = reinterpret_cast<const float4*>(g_Sp);
    float4 a = p[i];
    #pragma unroll
    for (int s = 1; s < KVSPLIT; s++) {
        float4 v = p[i + (size_t)s * SS];
        a.x += v.x; a.y += v.y; a.z += v.z; a.w += v.w;
    }
    reinterpret_cast<float4*>(g_S)[i] = a;
}

// ---------------------------------------------------------------------------
// K5: U = wo @ Wv (batch-independent) and wt = wo @ bv. fp32, tiny.
// ---------------------------------------------------------------------------
__global__ __launch_bounds__(256) void k_prep(const float* __restrict__ wo,
                                              const float* __restrict__ wv,
                                              const float* __restrict__ bv) {
    const int o0 = blockIdx.y * 64, e0 = blockIdx.x * 64;
    const int tid = threadIdx.x;
    if (blockIdx.x == 0 && tid < 64) {        // wt for this o-range
        const float* wr = wo + (size_t)(o0 + tid) * CDIM;
        float s = 0.f;
        for (int d = 0; d < CDIM; d += 4) {
            float4 w4 = *(const float4*)(wr + d);
            float4 b4 = *(const float4*)(bv + d);
            s += w4.x * b4.x + w4.y * b4.y + w4.z * b4.z + w4.w * b4.w;
        }
        g_wt[o0 + tid] = s;
    }

    __shared__ float As[16][64];
    __shared__ float Bs[16][64];
    const int arow = tid >> 2, acol = (tid & 3) << 2;   // A^T staging
    const int brow = tid >> 4, bcol = (tid & 15) << 2;  // B row-major staging
    const int tx = (tid & 15) << 2, ty = (tid >> 4) << 2;

    float acc[4][4];
    #pragma unroll
    for (int i = 0; i < 4; i++)
        #pragma unroll
        for (int j = 0; j < 4; j++) acc[i][j] = 0.f;

    for (int k0 = 0; k0 < CDIM; k0 += 16) {
        float4 av = *(const float4*)(wo + (size_t)(o0 + arow) * CDIM + k0 + acol);
        As[acol + 0][arow] = av.x; As[acol + 1][arow] = av.y;
        As[acol + 2][arow] = av.z; As[acol + 3][arow] = av.w;
        *(float4*)&Bs[brow][bcol] =
            *(const float4*)(wv + (size_t)(k0 + brow) * CDIM + e0 + bcol);
        __syncthreads();
        #pragma unroll
        for (int k = 0; k < 16; k++) {
            float4 a4 = *(const float4*)&As[k][ty];
            float4 b4 = *(const float4*)&Bs[k][tx];
            float a[4] = {a4.x, a4.y, a4.z, a4.w};
            float bb[4] = {b4.x, b4.y, b4.z, b4.w};
            #pragma unroll
            for (int i = 0; i < 4; i++)
                #pragma unroll
                for (int j = 0; j < 4; j++)
                    acc[i][j] = fmaf(a[i], bb[j], acc[i][j]);
        }
        __syncthreads();
    }
    #pragma unroll
    for (int i = 0; i < 4; i++)
        *(float4*)(g_U + (size_t)(o0 + ty + i) * CDIM + e0 + tx) =
            make_float4(acc[i][0], acc[i][1], acc[i][2], acc[i][3]);
}

// ---------------------------------------------------------------------------
// K6: M[b][o][c] = sum_e U[o,e] S[b][c,e] + wt[o] * k1[b][c]. fp32, tiny.
// ---------------------------------------------------------------------------
__global__ __launch_bounds__(256) void k_M() {
    const int b  = blockIdx.z;
    const int o0 = blockIdx.y * 64, c0 = blockIdx.x * 64;
    const float* Sb = g_S + (size_t)b * CDIM * CDIM;

    __shared__ float As[16][64];
    __shared__ float Bs[16][64];
    const int tid  = threadIdx.x;
    const int arow = tid >> 2, acol = (tid & 3) << 2;
    const int tx = (tid & 15) << 2, ty = (tid >> 4) << 2;

    float acc[4][4];
    #pragma unroll
    for (int i = 0; i < 4; i++)
        #pragma unroll
        for (int j = 0; j < 4; j++) acc[i][j] = 0.f;

    for (int k0 = 0; k0 < CDIM; k0 += 16) {
        float4 av = *(const float4*)(g_U + (size_t)(o0 + arow) * CDIM + k0 + acol);
        As[acol + 0][arow] = av.x; As[acol + 1][arow] = av.y;
        As[acol + 2][arow] = av.z; As[acol + 3][arow] = av.w;
        float4 bv = *(const float4*)(Sb + (size_t)(c0 + arow) * CDIM + k0 + acol);
        Bs[acol + 0][arow] = bv.x; Bs[acol + 1][arow] = bv.y;
        Bs[acol + 2][arow] = bv.z; Bs[acol + 3][arow] = bv.w;
        __syncthreads();
        #pragma unroll
        for (int k = 0; k < 16; k++) {
            float4 a4 = *(const float4*)&As[k][ty];
            float4 b4 = *(const float4*)&Bs[k][tx];
            float a[4] = {a4.x, a4.y, a4.z, a4.w};
            float bb[4] = {b4.x, b4.y, b4.z, b4.w};
            #pragma unroll
            for (int i = 0; i < 4; i++)
                #pragma unroll
                for (int j = 0; j < 4; j++)
                    acc[i][j] = fmaf(a[i], bb[j], acc[i][j]);
        }
        __syncthreads();
    }
    float* Mb = g_M + (size_t)b * CDIM * CDIM;
    const float* k1b = g_k1 + b * CDIM;
    #pragma unroll
    for (int i = 0; i < 4; i++) {
        const float w = g_wt[o0 + ty + i];
        *(float4*)(Mb + (size_t)(o0 + ty + i) * CDIM + c0 + tx) = make_float4(
            acc[i][0] + w * k1b[c0 + tx + 0], acc[i][1] + w * k1b[c0 + tx + 1],
            acc[i][2] + w * k1b[c0 + tx + 2], acc[i][3] + w * k1b[c0 + tx + 3]);
    }
}

// ---------------------------------------------------------------------------
// K7: out[b][o][n] = x[b][o][n] + M[b][o,:] . Q[:,n] + bo[o].
// ---------------------------------------------------------------------------
__global__ __launch_bounds__(256, 2) void k_out_t(const float* __restrict__ x,
                                                  const float* __restrict__ bo,
                                                  float* __restrict__ out) {
    extern __shared__ uint32_t smp[];
    uint32_t* As = smp;
    uint32_t* Bs = smp + 4096;
    const int b  = blockIdx.z;
    const int o0 = blockIdx.y * 128, n0 = blockIdx.x * 128;
    const float* Mb = g_M + (size_t)b * CDIM * CDIM;
    const float* Qf = g_qkv + (size_t)b * 2 * CDIM * NDIM;   // q plane [c][n]

    float C[2][8][4];
    #pragma unroll
    for (int mt = 0; mt < 2; mt++)
        #pragma unroll
        for (int nt = 0; nt < 8; nt++)
            #pragma unroll
            for (int r = 0; r < 4; r++) C[mt][nt][r] = 0.f;

    mma_block<16, 0, false>(Mb + (size_t)o0 * CDIM, CDIM,
                            Qf + n0, NDIM,
                            nullptr, nullptr, nullptr, 1.f, 0.f, As, Bs, C);

    const int lane = threadIdx.x & 31, wid = threadIdx.x >> 5;
    const int g = lane >> 2, t = lane & 3, wm = wid & 3, wn = wid >> 2;
    const float* xb = x   + ((size_t)b * CDIM + o0) * NDIM + n0;
    float*       ob = out + ((size_t)b * CDIM + o0) * NDIM + n0;
    #pragma unroll
    for (int mt = 0; mt < 2; mt++) {
        const int r0 = wm * 32 + mt * 16 + g;
        const float b0v = bo[o0 + r0], b1v = bo[o0 + r0 + 8];
        #pragma unroll
        for (int nt = 0; nt < 8; nt++) {
            const int col = wn * 64 + nt * 8 + 2 * t;
            float2 x0 = *(const float2*)(xb + (size_t)r0 * NDIM + col);
            float2 x1 = *(const float2*)(xb + (size_t)(r0 + 8) * NDIM + col);
            *(float2*)(ob + (size_t)r0 * NDIM + col) =
                make_float2(C[mt][nt][0] + b0v + x0.x, C[mt][nt][1] + b0v + x0.y);
            *(float2*)(ob + (size_t)(r0 + 8) * NDIM + col) =
                make_float2(C[mt][nt][2] + b1v + x1.x, C[mt][nt][3] + b1v + x1.y);
        }
    }
}

// ---------------------------------------------------------------------------
#define MMA_SMEM 32768
extern "C" void kernel_launch(void* const* d_in, const int* in_sizes, int n_in,
                              void* d_out, int out_size) {
    const float* x     = (const float*)d_in[0];
    const float* gamma = (const float*)d_in[1];
    const float* beta  = (const float*)d_in[2];
    const float* wq    = (const float*)d_in[3];
    const float* bq    = (const float*)d_in[4];
    const float* wk    = (const float*)d_in[5];
    const float* bk    = (const float*)d_in[6];
    const float* wv    = (const float*)d_in[7];
    const float* bv    = (const float*)d_in[8];
    const float* wo    = (const float*)d_in[9];
    const float* bo    = (const float*)d_in[10];
    float* out = (float*)d_out;

    cudaFuncSetAttribute(k_qkv_t, cudaFuncAttributeMaxDynamicSharedMemorySize, MMA_SMEM);
    cudaFuncSetAttribute(k_S,     cudaFuncAttributeMaxDynamicSharedMemorySize, MMA_SMEM);
    cudaFuncSetAttribute(k_out_t, cudaFuncAttributeMaxDynamicSharedMemorySize, MMA_SMEM);

    k_stats<<<BATCH * GRP, 256>>>(x);
    k_prep<<<dim3(4, 4), 256>>>(wo, wv, bv);
    k_qkv_t<<<dim3(NDIM / 128, 4, BATCH), 256, MMA_SMEM>>>(x, wq, bq, wk, bk, gamma, beta);
    k_S<<<dim3(2, 2, BATCH * KVSPLIT), 256, MMA_SMEM>>>(x, gamma, beta);
    k_red<<<(BATCH * CDIM * CDIM) / (256 * 4), 256>>>();
    k_M<<<dim3(4, 4, BATCH), 256>>>();
    k_out_t<<<dim3(NDIM / 128, 2, BATCH), 256, MMA_SMEM>>>(x, bo, out);
}

// round 12
// speedup vs baseline: 1.5714x; 1.2403x over previous
#include <cuda_runtime.h>
#include <math.h>
#include <stdint.h>

// Problem dims (LinearAttnBlock: B=8, C=256, H=W=64)
#define BATCH 8
#define CDIM  256
#define NDIM  4096
#define GRP   32
#define KVSPLIT 8

// ---------------- scratch (__device__ globals; no allocation allowed) ------
__device__ float  g_qkv[(size_t)BATCH * 2 * CDIM * NDIM];        // [b][q/k][c][n]
__device__ float  g_Sp [(size_t)KVSPLIT * BATCH * CDIM * CDIM];  // S split partials
__device__ float  g_S  [BATCH * CDIM * CDIM];                    // [b][c][e] = K.h^T
__device__ float  g_M  [BATCH * CDIM * CDIM];                    // [b][o][c]
__device__ float  g_U  [CDIM * CDIM];                            // wo @ Wv
__device__ float  g_wt [CDIM];                                   // wo @ bv
__device__ float  g_k1 [BATCH * CDIM];                           // rowsum of K
__device__ float2 g_stats[BATCH * GRP];                          // (mean, rstd)

// ---------------- tf32 mma.sync micro-kernel ------------------------------
static __device__ __forceinline__ uint32_t to_tf32(float f) {
    uint32_t r;
    asm("cvt.rna.tf32.f32 %0, %1;" : "=r"(r) : "f"(f));
    return r;
}

static __device__ __forceinline__ void mma_tf32(float c[4], const uint4& a, const uint2& b) {
    asm volatile(
        "mma.sync.aligned.m16n8k8.row.col.f32.tf32.tf32.f32 "
        "{%0,%1,%2,%3}, {%4,%5,%6,%7}, {%8,%9}, {%0,%1,%2,%3};"
        : "+f"(c[0]), "+f"(c[1]), "+f"(c[2]), "+f"(c[3])
        : "r"(a.x), "r"(a.y), "r"(a.z), "r"(a.w), "r"(b.x), "r"(b.y));
}

#define GNAPPLY(v, s, h) do { \
    (v).x = fmaf((v).x, (s), (h)); (v).y = fmaf((v).y, (s), (h)); \
    (v).z = fmaf((v).z, (s), (h)); (v).w = fmaf((v).w, (s), (h)); } while (0)

// C[128,128] += A[128, NC*16] * B(k,n)[NC*16, 128] (tf32, fp32 acc).
// BK=16 double-buffered stages; 2 CTAs/SM via __launch_bounds__(256,2).
//
// A SMEM layout (unchanged): word = ((mt*2+ks)*32 + g*4 + t)*4 + ahi + 2*kh,
//   xor ((g>>1)&3)<<2. Staging threads own a ROW-PAIR (r, r+8) x 4 k so the
//   (ahi 0,1) pair is one STS.64; store addresses are loop-invariant.
// B SMEM layout (nt-paired): word = ((nt2*2+ks)*32 + g*4 + t)*4 + (nt&1)*2 + kh,
//   xor ((nt2 ^ (g>>1))&7)<<2.  Staging threads own a KH-PAIR -> STS.64;
//   frag loads are lds.128 covering TWO nt fragments each.
// All stores 2-way conflict max; frag loads conflict-free.
template <int NC, int BMODE, bool GN>
static __device__ __forceinline__ void mma_block(
    const float* __restrict__ A, int lda,
    const float* __restrict__ B, int ldb,
    const float2* __restrict__ stats,
    const float* __restrict__ gamma, const float* __restrict__ beta,
    float scB, float shB,
    uint32_t* __restrict__ As, uint32_t* __restrict__ Bs,
    float C[2][8][4])
{
    const int tid = threadIdx.x;
    const int lane = tid & 31, wid = tid >> 5;
    const int wm = wid & 3, wn = wid >> 2;

    // ---- A staging: thread -> (row-pair rp, k-quad j) ----
    const int arp = tid >> 2, aj = tid & 3;
    const int amt = arp >> 3, ag = arp & 7;
    const int arow = amt * 16 + ag;            // second row = arow + 8
    const int akoff = aj << 2;                 // 4 contiguous k
    int aidx[4];
    {
        const int aks = aj >> 1, akh = aj & 1;
        const int axor = ((ag >> 1) & 3) << 2;
        const int aw0 = ((amt * 2 + aks) * 32 + ag * 4) * 4 + 2 * akh;
        #pragma unroll
        for (int t = 0; t < 4; t++) aidx[t] = (aw0 + 4 * t) ^ axor;
    }

    // ---- B staging mapping + loop-invariant store indices ----
    int bidx[4];
    int b0r0 = 0, b0r1 = 0;          // BMODE0: two k-rows within chunk
    const int b0n = lane << 2;       // BMODE0: 4 n's
    int b1col = 0, b1k0 = 0;         // BMODE1: column, k-base within chunk
    if (BMODE == 0) {
        const int ks = wid >> 2, t = wid & 3;
        b0r0 = ks * 8 + t; b0r1 = b0r0 + 4;
        #pragma unroll
        for (int m = 0; m < 4; m++) {
            const int n = b0n + m;
            const int gg = n & 7, ntl = (n >> 3) & 1, nt2 = n >> 4;
            const int w = ((nt2 * 2 + ks) * 32 + gg * 4 + t) * 4 + ntl * 2;
            bidx[m] = w ^ (((nt2 ^ (gg >> 1)) & 7) << 2);
        }
    } else {
        b1col = tid >> 1;
        const int ks = tid & 1;
        b1k0 = ks * 8;
        const int gg = b1col & 7, ntl = (b1col >> 3) & 1, nt2 = b1col >> 4;
        #pragma unroll
        for (int t = 0; t < 4; t++) {
            const int w = ((nt2 * 2 + ks) * 32 + gg * 4 + t) * 4 + ntl * 2;
            bidx[t] = w ^ (((nt2 ^ (gg >> 1)) & 7) << 2);
        }
    }

    float4 ra0, ra1, rb0, rb1;
    float sc0 = scB, sh0 = shB, sc1 = scB, sh1 = shB;

    // ---- prologue: chunk 0 into regs ----
    {
        const float* pa = A + (size_t)arow * lda + akoff;
        ra0 = *(const float4*)pa;
        ra1 = *(const float4*)(pa + 8 * (size_t)lda);
        if (BMODE == 0) {
            if (GN) {
                float2 m0 = stats[b0r0 >> 3];
                sc0 = m0.y * gamma[b0r0]; sh0 = fmaf(-m0.x, sc0, beta[b0r0]);
                float2 m1 = stats[b0r1 >> 3];
                sc1 = m1.y * gamma[b0r1]; sh1 = fmaf(-m1.x, sc1, beta[b0r1]);
            }
            rb0 = *(const float4*)(B + (size_t)b0r0 * ldb + b0n);
            rb1 = *(const float4*)(B + (size_t)b0r1 * ldb + b0n);
            if (GN) { GNAPPLY(rb0, sc0, sh0); GNAPPLY(rb1, sc1, sh1); }
        } else {
            const float* pb = B + (size_t)b1col * ldb + b1k0;
            rb0 = *(const float4*)pb;
            rb1 = *(const float4*)(pb + 4);
            if (GN) { GNAPPLY(rb0, sc0, sh0); GNAPPLY(rb1, sc0, sh0); }
        }
    }

    #pragma unroll 1
    for (int i = 0; i < NC; i++) {
        uint32_t* Asb = As + (i & 1) * 2048;
        uint32_t* Bsb = Bs + (i & 1) * 2048;
        // ---- store regs -> SMEM stage (STS.64, precomputed addresses) ----
        {
            const float a0[4] = {ra0.x, ra0.y, ra0.z, ra0.w};
            const float a1[4] = {ra1.x, ra1.y, ra1.z, ra1.w};
            #pragma unroll
            for (int t = 0; t < 4; t++) {
                uint2 st; st.x = to_tf32(a0[t]); st.y = to_tf32(a1[t]);
                *(uint2*)&Asb[aidx[t]] = st;
            }
            const float v0[4] = {rb0.x, rb0.y, rb0.z, rb0.w};
            const float v1[4] = {rb1.x, rb1.y, rb1.z, rb1.w};
            #pragma unroll
            for (int m = 0; m < 4; m++) {
                uint2 st; st.x = to_tf32(v0[m]); st.y = to_tf32(v1[m]);
                *(uint2*)&Bsb[bidx[m]] = st;
            }
        }
        __syncthreads();   // single sync per chunk (double-buffered stages)

        // ---- prefetch chunk i+1 (overlaps with mma below) ----
        if (i + 1 < NC) {
            const float* pa = A + (i + 1) * 16 + (size_t)arow * lda + akoff;
            ra0 = *(const float4*)pa;
            ra1 = *(const float4*)(pa + 8 * (size_t)lda);
            if (BMODE == 0) {
                const int c0 = (i + 1) * 16 + b0r0, c1 = c0 + 4;
                if (GN) {
                    float2 m0 = stats[c0 >> 3];
                    sc0 = m0.y * gamma[c0]; sh0 = fmaf(-m0.x, sc0, beta[c0]);
                    float2 m1 = stats[c1 >> 3];
                    sc1 = m1.y * gamma[c1]; sh1 = fmaf(-m1.x, sc1, beta[c1]);
                }
                rb0 = *(const float4*)(B + (size_t)c0 * ldb + b0n);
                rb1 = *(const float4*)(B + (size_t)c1 * ldb + b0n);
                if (GN) { GNAPPLY(rb0, sc0, sh0); GNAPPLY(rb1, sc1, sh1); }
            } else {
                const float* pb = B + (size_t)b1col * ldb + (i + 1) * 16 + b1k0;
                rb0 = *(const float4*)pb;
                rb1 = *(const float4*)(pb + 4);
                if (GN) { GNAPPLY(rb0, sc0, sh0); GNAPPLY(rb1, sc0, sh0); }
            }
        }

        // ---- compute: 2 k-steps x (2 m-tiles x 8 n-tiles) mma ----
        #pragma unroll
        for (int ks = 0; ks < 2; ks++) {
            uint4 af[2];
            #pragma unroll
            for (int mt = 0; mt < 2; mt++)
                af[mt] = *(const uint4*)&Asb[
                    ((((wm * 2 + mt) * 2 + ks) * 32 + lane) * 4) ^ (((lane >> 3) & 3) << 2)];
            #pragma unroll
            for (int q = 0; q < 4; q++) {
                const int NT2 = wn * 4 + q;
                uint4 bf = *(const uint4*)&Bsb[
                    (((NT2 * 2 + ks) * 32 + lane) * 4) ^ (((NT2 ^ (lane >> 3)) & 7) << 2)];
                const uint2 blo = make_uint2(bf.x, bf.y);
                const uint2 bhi = make_uint2(bf.z, bf.w);
                #pragma unroll
                for (int mt = 0; mt < 2; mt++) {
                    mma_tf32(C[mt][2 * q + 0], af[mt], blo);
                    mma_tf32(C[mt][2 * q + 1], af[mt], bhi);
                }
            }
        }
    }
    __syncthreads();   // protect SMEM reuse by epilogues
}

// ---------------------------------------------------------------------------
// K1: GroupNorm statistics (one block per (b,g)) + zero g_k1 for this replay.
// ---------------------------------------------------------------------------
__global__ __launch_bounds__(256) void k_stats(const float* __restrict__ x) {
    const int bg = blockIdx.x;
    if (threadIdx.x < 8) g_k1[bg * 8 + threadIdx.x] = 0.f;
    const float4* p = reinterpret_cast<const float4*>(x + (size_t)bg * 8 * NDIM);
    float s = 0.f, s2 = 0.f;
    for (int i = threadIdx.x; i < 8 * NDIM / 4; i += 256) {
        float4 v = p[i];
        s  += v.x + v.y + v.z + v.w;
        s2 += v.x * v.x + v.y * v.y + v.z * v.z + v.w * v.w;
    }
    __shared__ float sh0[8], sh1[8];
    #pragma unroll
    for (int o = 16; o > 0; o >>= 1) {
        s  += __shfl_down_sync(0xffffffffu, s,  o);
        s2 += __shfl_down_sync(0xffffffffu, s2, o);
    }
    const int lane = threadIdx.x & 31, w = threadIdx.x >> 5;
    if (lane == 0) { sh0[w] = s; sh1[w] = s2; }
    __syncthreads();
    if (w == 0) {
        s  = (lane < 8) ? sh0[lane] : 0.f;
        s2 = (lane < 8) ? sh1[lane] : 0.f;
        #pragma unroll
        for (int o = 4; o > 0; o >>= 1) {
            s  += __shfl_down_sync(0xffffffffu, s,  o);
            s2 += __shfl_down_sync(0xffffffffu, s2, o);
        }
        if (lane == 0) {
            const float inv = 1.f / (8.f * NDIM);
            float mean = s * inv;
            float var  = s2 * inv - mean * mean;
            g_stats[bg] = make_float2(mean, rsqrtf(var + 1e-6f));
        }
    }
}

// ---------------------------------------------------------------------------
// K2: Q,K = W_{q,k} @ GN(x) via tf32 mma.sync (GN folded into B staging).
// bias + elu+1 epilogue; K path also accumulates k1 rowsums (atomicAdd).
// ---------------------------------------------------------------------------
__global__ __launch_bounds__(256, 2) void k_qkv_t(
    const float* __restrict__ x,
    const float* __restrict__ wq, const float* __restrict__ bq,
    const float* __restrict__ wk, const float* __restrict__ bk,
    const float* __restrict__ gamma, const float* __restrict__ beta)
{
    extern __shared__ uint32_t smp[];
    uint32_t* As = smp;            // 2 x 2048
    uint32_t* Bs = smp + 4096;     // 2 x 2048
    const int b  = blockIdx.z;
    const int by = blockIdx.y;            // 0..3
    const int which = by >> 1;            // 0=q 1=k
    const int m0 = (by & 1) * 128;
    const int n0 = blockIdx.x * 128;
    const float* W    = which == 0 ? wq : wk;
    const float* bias = which == 0 ? bq : bk;

    float C[2][8][4];
    #pragma unroll
    for (int mt = 0; mt < 2; mt++)
        #pragma unroll
        for (int nt = 0; nt < 8; nt++)
            #pragma unroll
            for (int r = 0; r < 4; r++) C[mt][nt][r] = 0.f;

    mma_block<16, 0, true>(W + (size_t)m0 * CDIM, CDIM,
                           x + (size_t)b * CDIM * NDIM + n0, NDIM,
                           g_stats + b * GRP, gamma, beta, 1.f, 0.f, As, Bs, C);

    const int lane = threadIdx.x & 31, wid = threadIdx.x >> 5;
    const int g = lane >> 2, t = lane & 3, wm = wid & 3, wn = wid >> 2;
    float* outp = g_qkv + (((size_t)b * 2 + which) * CDIM + m0) * NDIM + n0;
    float rs0[2] = {0.f, 0.f}, rs1[2] = {0.f, 0.f};
    #pragma unroll
    for (int mt = 0; mt < 2; mt++) {
        const int r0 = wm * 32 + mt * 16 + g;
        const float b0v = bias[m0 + r0], b1v = bias[m0 + r0 + 8];
        #pragma unroll
        for (int nt = 0; nt < 8; nt++) {
            const int col = wn * 64 + nt * 8 + 2 * t;
            float v0 = C[mt][nt][0] + b0v, v1 = C[mt][nt][1] + b0v;
            float v2 = C[mt][nt][2] + b1v, v3 = C[mt][nt][3] + b1v;
            v0 = (v0 > 0.f) ? (v0 + 1.f) : expf(v0);   // elu+1
            v1 = (v1 > 0.f) ? (v1 + 1.f) : expf(v1);
            v2 = (v2 > 0.f) ? (v2 + 1.f) : expf(v2);
            v3 = (v3 > 0.f) ? (v3 + 1.f) : expf(v3);
            rs0[mt] += v0 + v1;
            rs1[mt] += v2 + v3;
            *(float2*)(outp + (size_t)r0 * NDIM + col)       = make_float2(v0, v1);
            *(float2*)(outp + (size_t)(r0 + 8) * NDIM + col) = make_float2(v2, v3);
        }
    }
    if (which == 1) {   // k1[c] = sum_n K[c,n]
        #pragma unroll
        for (int mt = 0; mt < 2; mt++) {
            float a = rs0[mt], c2 = rs1[mt];
            a  += __shfl_xor_sync(0xffffffffu, a,  1);
            a  += __shfl_xor_sync(0xffffffffu, a,  2);
            c2 += __shfl_xor_sync(0xffffffffu, c2, 1);
            c2 += __shfl_xor_sync(0xffffffffu, c2, 2);
            if (t == 0) {
                const int r0 = wm * 32 + mt * 16 + g;
                atomicAdd(&g_k1[b * CDIM + m0 + r0], a);
                atomicAdd(&g_k1[b * CDIM + m0 + r0 + 8], c2);
            }
        }
    }
}

// ---------------------------------------------------------------------------
// K3: S partials. Sp[sp][b][c][e] = sum_{n in split} K[c,n] * GN(x)[e,n].
// GN fold is a per-thread constant (col e fixed per staging thread).
// ---------------------------------------------------------------------------
__global__ __launch_bounds__(256, 2) void k_S(const float* __restrict__ x,
                                              const float* __restrict__ gamma,
                                              const float* __restrict__ beta) {
    extern __shared__ uint32_t smp[];
    uint32_t* As = smp;
    uint32_t* Bs = smp + 4096;
    const int z = blockIdx.z;
    const int b = z / KVSPLIT, sp = z % KVSPLIT;
    const int c0 = blockIdx.y * 128, e0 = blockIdx.x * 128;
    const int nb = sp * (NDIM / KVSPLIT);
    const float* Kf = g_qkv + ((size_t)b * 2 + 1) * CDIM * NDIM;

    const int e = e0 + (threadIdx.x >> 1);     // staging col for BMODE 1
    float2 ms = g_stats[b * GRP + (e >> 3)];
    const float sc = ms.y * gamma[e];
    const float sh = fmaf(-ms.x, sc, beta[e]);

    float C[2][8][4];
    #pragma unroll
    for (int mt = 0; mt < 2; mt++)
        #pragma unroll
        for (int nt = 0; nt < 8; nt++)
            #pragma unroll
            for (int r = 0; r < 4; r++) C[mt][nt][r] = 0.f;

    mma_block<(NDIM / KVSPLIT) / 16, 1, true>(
        Kf + (size_t)c0 * NDIM + nb, NDIM,
        x + ((size_t)b * CDIM + e0) * NDIM + nb, NDIM,
        nullptr, nullptr, nullptr, sc, sh, As, Bs, C);

    const int lane = threadIdx.x & 31, wid = threadIdx.x >> 5;
    const int g = lane >> 2, t = lane & 3, wm = wid & 3, wn = wid >> 2;
    float* dst = g_Sp + ((size_t)sp * BATCH + b) * CDIM * CDIM;
    #pragma unroll
    for (int mt = 0; mt < 2; mt++) {
        const int r0 = c0 + wm * 32 + mt * 16 + g;
        #pragma unroll
        for (int nt = 0; nt < 8; nt++) {
            const int col = e0 + wn * 64 + nt * 8 + 2 * t;
            *(float2*)(dst + (size_t)r0 * CDIM + col)       = make_float2(C[mt][nt][0], C[mt][nt][1]);
            *(float2*)(dst + (size_t)(r0 + 8) * CDIM + col) = make_float2(C[mt][nt][2], C[mt][nt][3]);
        }
    }
}

// ---------------------------------------------------------------------------
// K4: streaming reduction of the 8 S partials.
// ---------------------------------------------------------------------------
__global__ __launch_bounds__(256) void k_red() {
    const size_t i = (size_t)blockIdx.x * 256 + threadIdx.x;   // float4 idx
    const size_t SS = (size_t)BATCH * CDIM * CDIM / 4;
    const float4* p = reinterpret_cast<const float4*>(g_Sp);
    float4 a = p[i];
    #pragma unroll
    for (int s = 1; s < KVSPLIT; s++) {
        float4 v = p[i + (size_t)s * SS];
        a.x += v.x; a.y += v.y; a.z += v.z; a.w += v.w;
    }
    reinterpret_cast<float4*>(g_S)[i] = a;
}

// ---------------------------------------------------------------------------
// K5: U = wo @ Wv (batch-independent) and wt = wo @ bv. fp32, tiny.
// ---------------------------------------------------------------------------
__global__ __launch_bounds__(256) void k_prep(const float* __restrict__ wo,
                                              const float* __restrict__ wv,
                                              const float* __restrict__ bv) {
    const int o0 = blockIdx.y * 64, e0 = blockIdx.x * 64;
    const int tid = threadIdx.x;
    if (blockIdx.x == 0 && tid < 64) {        // wt for this o-range
        const float* wr = wo + (size_t)(o0 + tid) * CDIM;
        float s = 0.f;
        for (int d = 0; d < CDIM; d += 4) {
            float4 w4 = *(const float4*)(wr + d);
            float4 b4 = *(const float4*)(bv + d);
            s += w4.x * b4.x + w4.y * b4.y + w4.z * b4.z + w4.w * b4.w;
        }
        g_wt[o0 + tid] = s;
    }

    __shared__ float As[16][64];
    __shared__ float Bs[16][64];
    const int arow = tid >> 2, acol = (tid & 3) << 2;   // A^T staging
    const int brow = tid >> 4, bcol = (tid & 15) << 2;  // B row-major staging
    const int tx = (tid & 15) << 2, ty = (tid >> 4) << 2;

    float acc[4][4];
    #pragma unroll
    for (int i = 0; i < 4; i++)
        #pragma unroll
        for (int j = 0; j < 4; j++) acc[i][j] = 0.f;

    for (int k0 = 0; k0 < CDIM; k0 += 16) {
        float4 av = *(const float4*)(wo + (size_t)(o0 + arow) * CDIM + k0 + acol);
        As[acol + 0][arow] = av.x; As[acol + 1][arow] = av.y;
        As[acol + 2][arow] = av.z; As[acol + 3][arow] = av.w;
        *(float4*)&Bs[brow][bcol] =
            *(const float4*)(wv + (size_t)(k0 + brow) * CDIM + e0 + bcol);
        __syncthreads();
        #pragma unroll
        for (int k = 0; k < 16; k++) {
            float4 a4 = *(const float4*)&As[k][ty];
            float4 b4 = *(const float4*)&Bs[k][tx];
            float a[4] = {a4.x, a4.y, a4.z, a4.w};
            float bb[4] = {b4.x, b4.y, b4.z, b4.w};
            #pragma unroll
            for (int i = 0; i < 4; i++)
                #pragma unroll
                for (int j = 0; j < 4; j++)
                    acc[i][j] = fmaf(a[i], bb[j], acc[i][j]);
        }
        __syncthreads();
    }
    #pragma unroll
    for (int i = 0; i < 4; i++)
        *(float4*)(g_U + (size_t)(o0 + ty + i) * CDIM + e0 + tx) =
            make_float4(acc[i][0], acc[i][1], acc[i][2], acc[i][3]);
}

// ---------------------------------------------------------------------------
// K6: M[b][o][c] = sum_e U[o,e] S[b][c,e] + wt[o] * k1[b][c]. fp32, tiny.
// ---------------------------------------------------------------------------
__global__ __launch_bounds__(256) void k_M() {
    const int b  = blockIdx.z;
    const int o0 = blockIdx.y * 64, c0 = blockIdx.x * 64;
    const float* Sb = g_S + (size_t)b * CDIM * CDIM;

    __shared__ float As[16][64];
    __shared__ float Bs[16][64];
    const int tid  = threadIdx.x;
    const int arow = tid >> 2, acol = (tid & 3) << 2;
    const int tx = (tid & 15) << 2, ty = (tid >> 4) << 2;

    float acc[4][4];
    #pragma unroll
    for (int i = 0; i < 4; i++)
        #pragma unroll
        for (int j = 0; j < 4; j++) acc[i][j] = 0.f;

    for (int k0 = 0; k0 < CDIM; k0 += 16) {
        float4 av = *(const float4*)(g_U + (size_t)(o0 + arow) * CDIM + k0 + acol);
        As[acol + 0][arow] = av.x; As[acol + 1][arow] = av.y;
        As[acol + 2][arow] = av.z; As[acol + 3][arow] = av.w;
        float4 bv = *(const float4*)(Sb + (size_t)(c0 + arow) * CDIM + k0 + acol);
        Bs[acol + 0][arow] = bv.x; Bs[acol + 1][arow] = bv.y;
        Bs[acol + 2][arow] = bv.z; Bs[acol + 3][arow] = bv.w;
        __syncthreads();
        #pragma unroll
        for (int k = 0; k < 16; k++) {
            float4 a4 = *(const float4*)&As[k][ty];
            float4 b4 = *(const float4*)&Bs[k][tx];
            float a[4] = {a4.x, a4.y, a4.z, a4.w};
            float bb[4] = {b4.x, b4.y, b4.z, b4.w};
            #pragma unroll
            for (int i = 0; i < 4; i++)
                #pragma unroll
                for (int j = 0; j < 4; j++)
                    acc[i][j] = fmaf(a[i], bb[j], acc[i][j]);
        }
        __syncthreads();
    }
    float* Mb = g_M + (size_t)b * CDIM * CDIM;
    const float* k1b = g_k1 + b * CDIM;
    #pragma unroll
    for (int i = 0; i < 4; i++) {
        const float w = g_wt[o0 + ty + i];
        *(float4*)(Mb + (size_t)(o0 + ty + i) * CDIM + c0 + tx) = make_float4(
            acc[i][0] + w * k1b[c0 + tx + 0], acc[i][1] + w * k1b[c0 + tx + 1],
            acc[i][2] + w * k1b[c0 + tx + 2], acc[i][3] + w * k1b[c0 + tx + 3]);
    }
}

// ---------------------------------------------------------------------------
// K7: out[b][o][n] = x[b][o][n] + M[b][o,:] . Q[:,n] + bo[o].
// ---------------------------------------------------------------------------
__global__ __launch_bounds__(256, 2) void k_out_t(const float* __restrict__ x,
                                                  const float* __restrict__ bo,
                                                  float* __restrict__ out) {
    extern __shared__ uint32_t smp[];
    uint32_t* As = smp;
    uint32_t* Bs = smp + 4096;
    const int b  = blockIdx.z;
    const int o0 = blockIdx.y * 128, n0 = blockIdx.x * 128;
    const float* Mb = g_M + (size_t)b * CDIM * CDIM;
    const float* Qf = g_qkv + (size_t)b * 2 * CDIM * NDIM;   // q plane [c][n]

    float C[2][8][4];
    #pragma unroll
    for (int mt = 0; mt < 2; mt++)
        #pragma unroll
        for (int nt = 0; nt < 8; nt++)
            #pragma unroll
            for (int r = 0; r < 4; r++) C[mt][nt][r] = 0.f;

    mma_block<16, 0, false>(Mb + (size_t)o0 * CDIM, CDIM,
                            Qf + n0, NDIM,
                            nullptr, nullptr, nullptr, 1.f, 0.f, As, Bs, C);

    const int lane = threadIdx.x & 31, wid = threadIdx.x >> 5;
    const int g = lane >> 2, t = lane & 3, wm = wid & 3, wn = wid >> 2;
    const float* xb = x   + ((size_t)b * CDIM + o0) * NDIM + n0;
    float*       ob = out + ((size_t)b * CDIM + o0) * NDIM + n0;
    #pragma unroll
    for (int mt = 0; mt < 2; mt++) {
        const int r0 = wm * 32 + mt * 16 + g;
        const float b0v = bo[o0 + r0], b1v = bo[o0 + r0 + 8];
        #pragma unroll
        for (int nt = 0; nt < 8; nt++) {
            const int col = wn * 64 + nt * 8 + 2 * t;
            float2 x0 = *(const float2*)(xb + (size_t)r0 * NDIM + col);
            float2 x1 = *(const float2*)(xb + (size_t)(r0 + 8) * NDIM + col);
            *(float2*)(ob + (size_t)r0 * NDIM + col) =
                make_float2(C[mt][nt][0] + b0v + x0.x, C[mt][nt][1] + b0v + x0.y);
            *(float2*)(ob + (size_t)(r0 + 8) * NDIM + col) =
                make_float2(C[mt][nt][2] + b1v + x1.x, C[mt][nt][3] + b1v + x1.y);
        }
    }
}

// ---------------------------------------------------------------------------
#define MMA_SMEM 32768
extern "C" void kernel_launch(void* const* d_in, const int* in_sizes, int n_in,
                              void* d_out, int out_size) {
    const float* x     = (const float*)d_in[0];
    const float* gamma = (const float*)d_in[1];
    const float* beta  = (const float*)d_in[2];
    const float* wq    = (const float*)d_in[3];
    const float* bq    = (const float*)d_in[4];
    const float* wk    = (const float*)d_in[5];
    const float* bk    = (const float*)d_in[6];
    const float* wv    = (const float*)d_in[7];
    const float* bv    = (const float*)d_in[8];
    const float* wo    = (const float*)d_in[9];
    const float* bo    = (const float*)d_in[10];
    float* out = (float*)d_out;

    cudaFuncSetAttribute(k_qkv_t, cudaFuncAttributeMaxDynamicSharedMemorySize, MMA_SMEM);
    cudaFuncSetAttribute(k_S,     cudaFuncAttributeMaxDynamicSharedMemorySize, MMA_SMEM);
    cudaFuncSetAttribute(k_out_t, cudaFuncAttributeMaxDynamicSharedMemorySize, MMA_SMEM);

    k_stats<<<BATCH * GRP, 256>>>(x);
    k_prep<<<dim3(4, 4), 256>>>(wo, wv, bv);
    k_qkv_t<<<dim3(NDIM / 128, 4, BATCH), 256, MMA_SMEM>>>(x, wq, bq, wk, bk, gamma, beta);
    k_S<<<dim3(2, 2, BATCH * KVSPLIT), 256, MMA_SMEM>>>(x, gamma, beta);
    k_red<<<(BATCH * CDIM * CDIM) / (256 * 4), 256>>>();
    k_M<<<dim3(4, 4, BATCH), 256>>>();
    k_out_t<<<dim3(NDIM / 128, 2, BATCH), 256, MMA_SMEM>>>(x, bo, out);
}

// round 13
// speedup vs baseline: 1.5914x; 1.0127x over previous
#include <cuda_runtime.h>
#include <math.h>
#include <stdint.h>

// Problem dims (LinearAttnBlock: B=8, C=256, H=W=64)
#define BATCH 8
#define CDIM  256
#define NDIM  4096
#define GRP   32
#define KVSPLIT 8

// ---------------- scratch (__device__ globals; no allocation allowed) ------
__device__ float  g_qkv[(size_t)BATCH * 2 * CDIM * NDIM];        // [b][q/k][c][n]
__device__ float  g_Sp [(size_t)KVSPLIT * BATCH * CDIM * CDIM];  // S split partials
__device__ float  g_S  [BATCH * CDIM * CDIM];                    // [b][c][e] = K.h^T
__device__ float  g_M  [BATCH * CDIM * CDIM];                    // [b][o][c]
__device__ float  g_U  [CDIM * CDIM];                            // wo @ Wv
__device__ float  g_wt [CDIM];                                   // wo @ bv
__device__ float  g_k1 [BATCH * CDIM];                           // rowsum of K
__device__ float2 g_stats[BATCH * GRP];                          // (mean, rstd)

// ---------------- tf32 mma.sync micro-kernel ------------------------------
static __device__ __forceinline__ uint32_t to_tf32(float f) {
    uint32_t r;
    asm("cvt.rna.tf32.f32 %0, %1;" : "=r"(r) : "f"(f));
    return r;
}

static __device__ __forceinline__ void mma_tf32(float c[4], const uint4& a, const uint2& b) {
    asm volatile(
        "mma.sync.aligned.m16n8k8.row.col.f32.tf32.tf32.f32 "
        "{%0,%1,%2,%3}, {%4,%5,%6,%7}, {%8,%9}, {%0,%1,%2,%3};"
        : "+f"(c[0]), "+f"(c[1]), "+f"(c[2]), "+f"(c[3])
        : "r"(a.x), "r"(a.y), "r"(a.z), "r"(a.w), "r"(b.x), "r"(b.y));
}

#define GNAPPLY(v, s, h) do { \
    (v).x = fmaf((v).x, (s), (h)); (v).y = fmaf((v).y, (s), (h)); \
    (v).z = fmaf((v).z, (s), (h)); (v).w = fmaf((v).w, (s), (h)); } while (0)

// C[128,128] += A[128, NC*16] * B(k,n)[NC*16, 128] (tf32, fp32 acc).
// BK=16 double-buffered stages; 2 CTAs/SM via __launch_bounds__(256,2).
// All SMEM store/frag addresses are precomputed in registers; the chunk loop
// is manually unrolled by 2 so the stage base (+0 / +2048 words) is a
// compile-time constant.
// A layout: word = ((mt*2+ks)*32 + g*4 + t)*4 + ahi + 2*kh, xor ((g>>1)&3)<<2
// B layout: word = ((nt2*2+ks)*32 + g*4 + t)*4 + (nt&1)*2 + kh,
//           xor ((nt2 ^ (g>>1))&7)<<2
// Stores are STS.64 (2-way max conflict); frag loads lds.128 conflict-free.
template <int NC, int BMODE, bool GN>
static __device__ __forceinline__ void mma_block(
    const float* __restrict__ A, int lda,
    const float* __restrict__ B, int ldb,
    const float2* __restrict__ stats,
    const float* __restrict__ gamma, const float* __restrict__ beta,
    float scB, float shB,
    uint32_t* __restrict__ As, uint32_t* __restrict__ Bs,
    float C[2][8][4])
{
    static_assert((NC & 1) == 0, "NC must be even");
    const int tid = threadIdx.x;
    const int lane = tid & 31, wid = tid >> 5;
    const int wm = wid & 3, wn = wid >> 2;

    // ---- A staging: thread -> (row-pair rp, k-quad j) ----
    const int arp = tid >> 2, aj = tid & 3;
    const int amt = arp >> 3, ag = arp & 7;
    const int arow = amt * 16 + ag;            // second row = arow + 8
    const int akoff = aj << 2;                 // 4 contiguous k
    int aidx[4];
    {
        const int aks = aj >> 1, akh = aj & 1;
        const int axor = ((ag >> 1) & 3) << 2;
        const int aw0 = ((amt * 2 + aks) * 32 + ag * 4) * 4 + 2 * akh;
        #pragma unroll
        for (int t = 0; t < 4; t++) aidx[t] = (aw0 + 4 * t) ^ axor;
    }

    // ---- B staging mapping + loop-invariant store indices ----
    int bidx[4];
    int b0r0 = 0, b0r1 = 0;          // BMODE0: two k-rows within chunk
    const int b0n = lane << 2;       // BMODE0: 4 n's
    int b1k0 = 0;                    // BMODE1: k-base within chunk
    const float* pBbase = B;
    if (BMODE == 0) {
        const int ks = wid >> 2, t = wid & 3;
        b0r0 = ks * 8 + t; b0r1 = b0r0 + 4;
        #pragma unroll
        for (int m = 0; m < 4; m++) {
            const int n = b0n + m;
            const int gg = n & 7, ntl = (n >> 3) & 1, nt2 = n >> 4;
            const int w = ((nt2 * 2 + ks) * 32 + gg * 4 + t) * 4 + ntl * 2;
            bidx[m] = w ^ (((nt2 ^ (gg >> 1)) & 7) << 2);
        }
    } else {
        const int b1col = tid >> 1;
        const int ks = tid & 1;
        b1k0 = ks * 8;
        const int gg = b1col & 7, ntl = (b1col >> 3) & 1, nt2 = b1col >> 4;
        #pragma unroll
        for (int t = 0; t < 4; t++) {
            const int w = ((nt2 * 2 + ks) * 32 + gg * 4 + t) * 4 + ntl * 2;
            bidx[t] = w ^ (((nt2 ^ (gg >> 1)) & 7) << 2);
        }
        pBbase = B + (size_t)b1col * ldb + b1k0;
    }
    const float* pAbase = A + (size_t)arow * lda + akoff;

    // ---- precomputed frag word-indices (loop-invariant) ----
    int afi[2][2], bfi[2][4];
    {
        const int axorf = ((lane >> 3) & 3) << 2;
        #pragma unroll
        for (int mt = 0; mt < 2; mt++)
            #pragma unroll
            for (int ks = 0; ks < 2; ks++)
                afi[mt][ks] = ((((wm * 2 + mt) * 2 + ks) * 32 + lane) * 4) ^ axorf;
        #pragma unroll
        for (int ks = 0; ks < 2; ks++)
            #pragma unroll
            for (int q = 0; q < 4; q++) {
                const int NT2 = wn * 4 + q;
                bfi[ks][q] = (((NT2 * 2 + ks) * 32 + lane) * 4)
                             ^ (((NT2 ^ (lane >> 3)) & 7) << 2);
            }
    }

    float4 ra0, ra1, rb0, rb1;
    float sc0 = scB, sh0 = shB, sc1 = scB, sh1 = shB;

    // ---- prefetch helper (loads chunk ic into regs) ----
    auto prefetch = [&](int ic) {
        const float* pa = pAbase + ic * 16;
        ra0 = *(const float4*)pa;
        ra1 = *(const float4*)(pa + 8 * (size_t)lda);
        if (BMODE == 0) {
            const int c0 = ic * 16 + b0r0, c1 = c0 + 4;
            if (GN) {
                float2 m0 = stats[c0 >> 3];
                sc0 = m0.y * gamma[c0]; sh0 = fmaf(-m0.x, sc0, beta[c0]);
                float2 m1 = stats[c1 >> 3];
                sc1 = m1.y * gamma[c1]; sh1 = fmaf(-m1.x, sc1, beta[c1]);
            }
            rb0 = *(const float4*)(pBbase + (size_t)c0 * ldb + b0n);
            rb1 = *(const float4*)(pBbase + (size_t)c1 * ldb + b0n);
            if (GN) { GNAPPLY(rb0, sc0, sh0); GNAPPLY(rb1, sc1, sh1); }
        } else {
            const float* pb = pBbase + ic * 16;
            rb0 = *(const float4*)pb;
            rb1 = *(const float4*)(pb + 4);
            if (GN) { GNAPPLY(rb0, sc0, sh0); GNAPPLY(rb1, sc0, sh0); }
        }
    };

    // ---- one pipeline step on stage SOFF (0 or 2048 words) ----
    auto chunk = [&](uint32_t* __restrict__ Asb, uint32_t* __restrict__ Bsb,
                     int inext, bool dopf) {
        {   // store regs -> SMEM stage (STS.64, precomputed addresses)
            const float a0[4] = {ra0.x, ra0.y, ra0.z, ra0.w};
            const float a1[4] = {ra1.x, ra1.y, ra1.z, ra1.w};
            #pragma unroll
            for (int t = 0; t < 4; t++) {
                uint2 st; st.x = to_tf32(a0[t]); st.y = to_tf32(a1[t]);
                *(uint2*)&Asb[aidx[t]] = st;
            }
            const float v0[4] = {rb0.x, rb0.y, rb0.z, rb0.w};
            const float v1[4] = {rb1.x, rb1.y, rb1.z, rb1.w};
            #pragma unroll
            for (int m = 0; m < 4; m++) {
                uint2 st; st.x = to_tf32(v0[m]); st.y = to_tf32(v1[m]);
                *(uint2*)&Bsb[bidx[m]] = st;
            }
        }
        __syncthreads();
        if (dopf) prefetch(inext);   // overlaps with mma below
        #pragma unroll
        for (int ks = 0; ks < 2; ks++) {
            uint4 af0 = *(const uint4*)&Asb[afi[0][ks]];
            uint4 af1 = *(const uint4*)&Asb[afi[1][ks]];
            #pragma unroll
            for (int q = 0; q < 4; q++) {
                uint4 bf = *(const uint4*)&Bsb[bfi[ks][q]];
                const uint2 blo = make_uint2(bf.x, bf.y);
                const uint2 bhi = make_uint2(bf.z, bf.w);
                mma_tf32(C[0][2 * q + 0], af0, blo);
                mma_tf32(C[0][2 * q + 1], af0, bhi);
                mma_tf32(C[1][2 * q + 0], af1, blo);
                mma_tf32(C[1][2 * q + 1], af1, bhi);
            }
        }
    };

    prefetch(0);
    #pragma unroll 1
    for (int i = 0; i < NC; i += 2) {
        chunk(As, Bs, i + 1, true);                       // stage 0
        chunk(As + 2048, Bs + 2048, i + 2, i + 2 < NC);   // stage 1
    }
    __syncthreads();
}

// ---------------------------------------------------------------------------
// K1: GroupNorm statistics (one block per (b,g)) + zero g_k1 for this replay.
// ---------------------------------------------------------------------------
__global__ __launch_bounds__(256) void k_stats(const float* __restrict__ x) {
    const int bg = blockIdx.x;
    if (threadIdx.x < 8) g_k1[bg * 8 + threadIdx.x] = 0.f;
    const float4* p = reinterpret_cast<const float4*>(x + (size_t)bg * 8 * NDIM);
    float s = 0.f, s2 = 0.f;
    for (int i = threadIdx.x; i < 8 * NDIM / 4; i += 256) {
        float4 v = p[i];
        s  += v.x + v.y + v.z + v.w;
        s2 += v.x * v.x + v.y * v.y + v.z * v.z + v.w * v.w;
    }
    __shared__ float sh0[8], sh1[8];
    #pragma unroll
    for (int o = 16; o > 0; o >>= 1) {
        s  += __shfl_down_sync(0xffffffffu, s,  o);
        s2 += __shfl_down_sync(0xffffffffu, s2, o);
    }
    const int lane = threadIdx.x & 31, w = threadIdx.x >> 5;
    if (lane == 0) { sh0[w] = s; sh1[w] = s2; }
    __syncthreads();
    if (w == 0) {
        s  = (lane < 8) ? sh0[lane] : 0.f;
        s2 = (lane < 8) ? sh1[lane] : 0.f;
        #pragma unroll
        for (int o = 4; o > 0; o >>= 1) {
            s  += __shfl_down_sync(0xffffffffu, s,  o);
            s2 += __shfl_down_sync(0xffffffffu, s2, o);
        }
        if (lane == 0) {
            const float inv = 1.f / (8.f * NDIM);
            float mean = s * inv;
            float var  = s2 * inv - mean * mean;
            g_stats[bg] = make_float2(mean, rsqrtf(var + 1e-6f));
        }
    }
}

// ---------------------------------------------------------------------------
// K2: Q,K = W_{q,k} @ GN(x) via tf32 mma.sync (GN folded into B staging).
// bias + elu+1 epilogue (__expf); K path also accumulates k1 rowsums.
// ---------------------------------------------------------------------------
__global__ __launch_bounds__(256, 2) void k_qkv_t(
    const float* __restrict__ x,
    const float* __restrict__ wq, const float* __restrict__ bq,
    const float* __restrict__ wk, const float* __restrict__ bk,
    const float* __restrict__ gamma, const float* __restrict__ beta)
{
    extern __shared__ uint32_t smp[];
    uint32_t* As = smp;            // 2 x 2048
    uint32_t* Bs = smp + 4096;     // 2 x 2048
    const int b  = blockIdx.z;
    const int by = blockIdx.y;            // 0..3
    const int which = by >> 1;            // 0=q 1=k
    const int m0 = (by & 1) * 128;
    const int n0 = blockIdx.x * 128;
    const float* W    = which == 0 ? wq : wk;
    const float* bias = which == 0 ? bq : bk;

    float C[2][8][4];
    #pragma unroll
    for (int mt = 0; mt < 2; mt++)
        #pragma unroll
        for (int nt = 0; nt < 8; nt++)
            #pragma unroll
            for (int r = 0; r < 4; r++) C[mt][nt][r] = 0.f;

    mma_block<16, 0, true>(W + (size_t)m0 * CDIM, CDIM,
                           x + (size_t)b * CDIM * NDIM + n0, NDIM,
                           g_stats + b * GRP, gamma, beta, 1.f, 0.f, As, Bs, C);

    const int lane = threadIdx.x & 31, wid = threadIdx.x >> 5;
    const int g = lane >> 2, t = lane & 3, wm = wid & 3, wn = wid >> 2;
    float* outp = g_qkv + (((size_t)b * 2 + which) * CDIM + m0) * NDIM + n0;
    float rs0[2] = {0.f, 0.f}, rs1[2] = {0.f, 0.f};
    #pragma unroll
    for (int mt = 0; mt < 2; mt++) {
        const int r0 = wm * 32 + mt * 16 + g;
        const float b0v = bias[m0 + r0], b1v = bias[m0 + r0 + 8];
        #pragma unroll
        for (int nt = 0; nt < 8; nt++) {
            const int col = wn * 64 + nt * 8 + 2 * t;
            float v0 = C[mt][nt][0] + b0v, v1 = C[mt][nt][1] + b0v;
            float v2 = C[mt][nt][2] + b1v, v3 = C[mt][nt][3] + b1v;
            v0 = (v0 > 0.f) ? (v0 + 1.f) : __expf(v0);   // elu+1 (fast exp)
            v1 = (v1 > 0.f) ? (v1 + 1.f) : __expf(v1);
            v2 = (v2 > 0.f) ? (v2 + 1.f) : __expf(v2);
            v3 = (v3 > 0.f) ? (v3 + 1.f) : __expf(v3);
            rs0[mt] += v0 + v1;
            rs1[mt] += v2 + v3;
            *(float2*)(outp + (size_t)r0 * NDIM + col)       = make_float2(v0, v1);
            *(float2*)(outp + (size_t)(r0 + 8) * NDIM + col) = make_float2(v2, v3);
        }
    }
    if (which == 1) {   // k1[c] = sum_n K[c,n]
        #pragma unroll
        for (int mt = 0; mt < 2; mt++) {
            float a = rs0[mt], c2 = rs1[mt];
            a  += __shfl_xor_sync(0xffffffffu, a,  1);
            a  += __shfl_xor_sync(0xffffffffu, a,  2);
            c2 += __shfl_xor_sync(0xffffffffu, c2, 1);
            c2 += __shfl_xor_sync(0xffffffffu, c2, 2);
            if (t == 0) {
                const int r0 = wm * 32 + mt * 16 + g;
                atomicAdd(&g_k1[b * CDIM + m0 + r0], a);
                atomicAdd(&g_k1[b * CDIM + m0 + r0 + 8], c2);
            }
        }
    }
}

// ---------------------------------------------------------------------------
// K3: S partials. Sp[sp][b][c][e] = sum_{n in split} K[c,n] * GN(x)[e,n].
// GN fold is a per-thread constant (col e fixed per staging thread).
// ---------------------------------------------------------------------------
__global__ __launch_bounds__(256, 2) void k_S(const float* __restrict__ x,
                                              const float* __restrict__ gamma,
                                              const float* __restrict__ beta) {
    extern __shared__ uint32_t smp[];
    uint32_t* As = smp;
    uint32_t* Bs = smp + 4096;
    const int z = blockIdx.z;
    const int b = z / KVSPLIT, sp = z % KVSPLIT;
    const int c0 = blockIdx.y * 128, e0 = blockIdx.x * 128;
    const int nb = sp * (NDIM / KVSPLIT);
    const float* Kf = g_qkv + ((size_t)b * 2 + 1) * CDIM * NDIM;

    const int e = e0 + (threadIdx.x >> 1);     // staging col for BMODE 1
    float2 ms = g_stats[b * GRP + (e >> 3)];
    const float sc = ms.y * gamma[e];
    const float sh = fmaf(-ms.x, sc, beta[e]);

    float C[2][8][4];
    #pragma unroll
    for (int mt = 0; mt < 2; mt++)
        #pragma unroll
        for (int nt = 0; nt < 8; nt++)
            #pragma unroll
            for (int r = 0; r < 4; r++) C[mt][nt][r] = 0.f;

    mma_block<(NDIM / KVSPLIT) / 16, 1, true>(
        Kf + (size_t)c0 * NDIM + nb, NDIM,
        x + ((size_t)b * CDIM + e0) * NDIM + nb, NDIM,
        nullptr, nullptr, nullptr, sc, sh, As, Bs, C);

    const int lane = threadIdx.x & 31, wid = threadIdx.x >> 5;
    const int g = lane >> 2, t = lane & 3, wm = wid & 3, wn = wid >> 2;
    float* dst = g_Sp + ((size_t)sp * BATCH + b) * CDIM * CDIM;
    #pragma unroll
    for (int mt = 0; mt < 2; mt++) {
        const int r0 = c0 + wm * 32 + mt * 16 + g;
        #pragma unroll
        for (int nt = 0; nt < 8; nt++) {
            const int col = e0 + wn * 64 + nt * 8 + 2 * t;
            *(float2*)(dst + (size_t)r0 * CDIM + col)       = make_float2(C[mt][nt][0], C[mt][nt][1]);
            *(float2*)(dst + (size_t)(r0 + 8) * CDIM + col) = make_float2(C[mt][nt][2], C[mt][nt][3]);
        }
    }
}

// ---------------------------------------------------------------------------
// K4: streaming reduction of the 8 S partials.
// ---------------------------------------------------------------------------
__global__ __launch_bounds__(256) void k_red() {
    const size_t i = (size_t)blockIdx.x * 256 + threadIdx.x;   // float4 idx
    const size_t SS = (size_t)BATCH * CDIM * CDIM / 4;
    const float4* p = reinterpret_cast<const float4*>(g_Sp);
    float4 a = p[i];
    #pragma unroll
    for (int s = 1; s < KVSPLIT; s++) {
        float4 v = p[i + (size_t)s * SS];
        a.x += v.x; a.y += v.y; a.z += v.z; a.w += v.w;
    }
    reinterpret_cast<float4*>(g_S)[i] = a;
}

// ---------------------------------------------------------------------------
// K5: U = wo @ Wv (batch-independent) and wt = wo @ bv. fp32, tiny.
// ---------------------------------------------------------------------------
__global__ __launch_bounds__(256) void k_prep(const float* __restrict__ wo,
                                              const float* __restrict__ wv,
                                              const float* __restrict__ bv) {
    const int o0 = blockIdx.y * 64, e0 = blockIdx.x * 64;
    const int tid = threadIdx.x;
    if (blockIdx.x == 0 && tid < 64) {        // wt for this o-range
        const float* wr = wo + (size_t)(o0 + tid) * CDIM;
        float s = 0.f;
        for (int d = 0; d < CDIM; d += 4) {
            float4 w4 = *(const float4*)(wr + d);
            float4 b4 = *(const float4*)(bv + d);
            s += w4.x * b4.x + w4.y * b4.y + w4.z * b4.z + w4.w * b4.w;
        }
        g_wt[o0 + tid] = s;
    }

    __shared__ float As[16][64];
    __shared__ float Bs[16][64];
    const int arow = tid >> 2, acol = (tid & 3) << 2;   // A^T staging
    const int brow = tid >> 4, bcol = (tid & 15) << 2;  // B row-major staging
    const int tx = (tid & 15) << 2, ty = (tid >> 4) << 2;

    float acc[4][4];
    #pragma unroll
    for (int i = 0; i < 4; i++)
        #pragma unroll
        for (int j = 0; j < 4; j++) acc[i][j] = 0.f;

    for (int k0 = 0; k0 < CDIM; k0 += 16) {
        float4 av = *(const float4*)(wo + (size_t)(o0 + arow) * CDIM + k0 + acol);
        As[acol + 0][arow] = av.x; As[acol + 1][arow] = av.y;
        As[acol + 2][arow] = av.z; As[acol + 3][arow] = av.w;
        *(float4*)&Bs[brow][bcol] =
            *(const float4*)(wv + (size_t)(k0 + brow) * CDIM + e0 + bcol);
        __syncthreads();
        #pragma unroll
        for (int k = 0; k < 16; k++) {
            float4 a4 = *(const float4*)&As[k][ty];
            float4 b4 = *(const float4*)&Bs[k][tx];
            float a[4] = {a4.x, a4.y, a4.z, a4.w};
            float bb[4] = {b4.x, b4.y, b4.z, b4.w};
            #pragma unroll
            for (int i = 0; i < 4; i++)
                #pragma unroll
                for (int j = 0; j < 4; j++)
                    acc[i][j] = fmaf(a[i], bb[j], acc[i][j]);
        }
        __syncthreads();
    }
    #pragma unroll
    for (int i = 0; i < 4; i++)
        *(float4*)(g_U + (size_t)(o0 + ty + i) * CDIM + e0 + tx) =
            make_float4(acc[i][0], acc[i][1], acc[i][2], acc[i][3]);
}

// ---------------------------------------------------------------------------
// K6: M[b][o][c] = sum_e U[o,e] S[b][c,e] + wt[o] * k1[b][c]. fp32, tiny.
// ---------------------------------------------------------------------------
__global__ __launch_bounds__(256) void k_M() {
    const int b  = blockIdx.z;
    const int o0 = blockIdx.y * 64, c0 = blockIdx.x * 64;
    const float* Sb = g_S + (size_t)b * CDIM * CDIM;

    __shared__ float As[16][64];
    __shared__ float Bs[16][64];
    const int tid  = threadIdx.x;
    const int arow = tid >> 2, acol = (tid & 3) << 2;
    const int tx = (tid & 15) << 2, ty = (tid >> 4) << 2;

    float acc[4][4];
    #pragma unroll
    for (int i = 0; i < 4; i++)
        #pragma unroll
        for (int j = 0; j < 4; j++) acc[i][j] = 0.f;

    for (int k0 = 0; k0 < CDIM; k0 += 16) {
        float4 av = *(const float4*)(g_U + (size_t)(o0 + arow) * CDIM + k0 + acol);
        As[acol + 0][arow] = av.x; As[acol + 1][arow] = av.y;
        As[acol + 2][arow] = av.z; As[acol + 3][arow] = av.w;
        float4 bv = *(const float4*)(Sb + (size_t)(c0 + arow) * CDIM + k0 + acol);
        Bs[acol + 0][arow] = bv.x; Bs[acol + 1][arow] = bv.y;
        Bs[acol + 2][arow] = bv.z; Bs[acol + 3][arow] = bv.w;
        __syncthreads();
        #pragma unroll
        for (int k = 0; k < 16; k++) {
            float4 a4 = *(const float4*)&As[k][ty];
            float4 b4 = *(const float4*)&Bs[k][tx];
            float a[4] = {a4.x, a4.y, a4.z, a4.w};
            float bb[4] = {b4.x, b4.y, b4.z, b4.w};
            #pragma unroll
            for (int i = 0; i < 4; i++)
                #pragma unroll
                for (int j = 0; j < 4; j++)
                    acc[i][j] = fmaf(a[i], bb[j], acc[i][j]);
        }
        __syncthreads();
    }
    float* Mb = g_M + (size_t)b * CDIM * CDIM;
    const float* k1b = g_k1 + b * CDIM;
    #pragma unroll
    for (int i = 0; i < 4; i++) {
        const float w = g_wt[o0 + ty + i];
        *(float4*)(Mb + (size_t)(o0 + ty + i) * CDIM + c0 + tx) = make_float4(
            acc[i][0] + w * k1b[c0 + tx + 0], acc[i][1] + w * k1b[c0 + tx + 1],
            acc[i][2] + w * k1b[c0 + tx + 2], acc[i][3] + w * k1b[c0 + tx + 3]);
    }
}

// ---------------------------------------------------------------------------
// K7: out[b][o][n] = x[b][o][n] + M[b][o,:] . Q[:,n] + bo[o].
// ---------------------------------------------------------------------------
__global__ __launch_bounds__(256, 2) void k_out_t(const float* __restrict__ x,
                                                  const float* __restrict__ bo,
                                                  float* __restrict__ out) {
    extern __shared__ uint32_t smp[];
    uint32_t* As = smp;
    uint32_t* Bs = smp + 4096;
    const int b  = blockIdx.z;
    const int o0 = blockIdx.y * 128, n0 = blockIdx.x * 128;
    const float* Mb = g_M + (size_t)b * CDIM * CDIM;
    const float* Qf = g_qkv + (size_t)b * 2 * CDIM * NDIM;   // q plane [c][n]

    float C[2][8][4];
    #pragma unroll
    for (int mt = 0; mt < 2; mt++)
        #pragma unroll
        for (int nt = 0; nt < 8; nt++)
            #pragma unroll
            for (int r = 0; r < 4; r++) C[mt][nt][r] = 0.f;

    mma_block<16, 0, false>(Mb + (size_t)o0 * CDIM, CDIM,
                            Qf + n0, NDIM,
                            nullptr, nullptr, nullptr, 1.f, 0.f, As, Bs, C);

    const int lane = threadIdx.x & 31, wid = threadIdx.x >> 5;
    const int g = lane >> 2, t = lane & 3, wm = wid & 3, wn = wid >> 2;
    const float* xb = x   + ((size_t)b * CDIM + o0) * NDIM + n0;
    float*       ob = out + ((size_t)b * CDIM + o0) * NDIM + n0;
    #pragma unroll
    for (int mt = 0; mt < 2; mt++) {
        const int r0 = wm * 32 + mt * 16 + g;
        const float b0v = bo[o0 + r0], b1v = bo[o0 + r0 + 8];
        #pragma unroll
        for (int nt = 0; nt < 8; nt++) {
            const int col = wn * 64 + nt * 8 + 2 * t;
            float2 x0 = *(const float2*)(xb + (size_t)r0 * NDIM + col);
            float2 x1 = *(const float2*)(xb + (size_t)(r0 + 8) * NDIM + col);
            *(float2*)(ob + (size_t)r0 * NDIM + col) =
                make_float2(C[mt][nt][0] + b0v + x0.x, C[mt][nt][1] + b0v + x0.y);
            *(float2*)(ob + (size_t)(r0 + 8) * NDIM + col) =
                make_float2(C[mt][nt][2] + b1v + x1.x, C[mt][nt][3] + b1v + x1.y);
        }
    }
}

// ---------------------------------------------------------------------------
#define MMA_SMEM 32768
extern "C" void kernel_launch(void* const* d_in, const int* in_sizes, int n_in,
                              void* d_out, int out_size) {
    const float* x     = (const float*)d_in[0];
    const float* gamma = (const float*)d_in[1];
    const float* beta  = (const float*)d_in[2];
    const float* wq    = (const float*)d_in[3];
    const float* bq    = (const float*)d_in[4];
    const float* wk    = (const float*)d_in[5];
    const float* bk    = (const float*)d_in[6];
    const float* wv    = (const float*)d_in[7];
    const float* bv    = (const float*)d_in[8];
    const float* wo    = (const float*)d_in[9];
    const float* bo    = (const float*)d_in[10];
    float* out = (float*)d_out;

    cudaFuncSetAttribute(k_qkv_t, cudaFuncAttributeMaxDynamicSharedMemorySize, MMA_SMEM);
    cudaFuncSetAttribute(k_S,     cudaFuncAttributeMaxDynamicSharedMemorySize, MMA_SMEM);
    cudaFuncSetAttribute(k_out_t, cudaFuncAttributeMaxDynamicSharedMemorySize, MMA_SMEM);

    k_stats<<<BATCH * GRP, 256>>>(x);
    k_prep<<<dim3(4, 4), 256>>>(wo, wv, bv);
    k_qkv_t<<<dim3(NDIM / 128, 4, BATCH), 256, MMA_SMEM>>>(x, wq, bq, wk, bk, gamma, beta);
    k_S<<<dim3(2, 2, BATCH * KVSPLIT), 256, MMA_SMEM>>>(x, gamma, beta);
    k_red<<<(BATCH * CDIM * CDIM) / (256 * 4), 256>>>();
    k_M<<<dim3(4, 4, BATCH), 256>>>();
    k_out_t<<<dim3(NDIM / 128, 2, BATCH), 256, MMA_SMEM>>>(x, bo, out);
}